// round 8
// baseline (speedup 1.0000x reference)
#include <cuda_runtime.h>
#include <cuda_bf16.h>
#include <math.h>
#include <stdint.h>

// ---------------- problem constants ----------------
#define T_TOK  2048
#define HID    4096
#define NH     32
#define DN     128   // qk_nope
#define DR     64    // qk_rope
#define DH     192   // qk_head
#define DV     128   // v_head
#define QL     1536  // q_lora
#define KVL    512   // kv_lora

// ---------------- device scratch ----------------
__device__ float g_qa    [(size_t)T_TOK * QL];
__device__ float g_q     [(size_t)T_TOK * NH * DH];
__device__ float g_kva   [(size_t)T_TOK * (KVL + DR)];
__device__ float g_kv    [(size_t)T_TOK * NH * (DN + DV)];
__device__ float g_kfull [(size_t)T_TOK * NH * DH];
__device__ float g_s     [(size_t)NH * T_TOK * T_TOK];
__device__ float g_attn  [(size_t)T_TOK * NH * DV];
__device__ float g_vt    [(size_t)NH * DV * T_TOK];     // v transposed per head [h][dv][t]
// tf32-rounded (and transposed, for weights) copies of raw inputs
__device__ float g_hidr  [(size_t)T_TOK * HID];
__device__ float g_wqa   [(size_t)QL * HID];            // [n][k]
__device__ float g_wqb   [(size_t)NH * DH * QL];        // [n][k]
__device__ float g_wkva  [(size_t)(KVL + DR) * HID];    // [n][k]
__device__ float g_wkvb  [(size_t)NH * (DN + DV) * KVL];// [n][k]
__device__ float g_wo    [(size_t)HID * NH * DV];       // [n][k]

// ---------------- helpers ----------------
__device__ __forceinline__ float round_tf32(float x) {
    float y;
    asm("cvt.rna.tf32.f32 %0, %1;" : "=f"(y) : "f"(x));
    return y;
}

__device__ __forceinline__ void mma_tf32(float* c, const uint32_t* a, const uint32_t* b) {
    asm volatile(
        "mma.sync.aligned.m16n8k8.row.col.f32.tf32.tf32.f32 "
        "{%0,%1,%2,%3}, {%4,%5,%6,%7}, {%8,%9}, {%0,%1,%2,%3};"
        : "+f"(c[0]), "+f"(c[1]), "+f"(c[2]), "+f"(c[3])
        : "r"(a[0]), "r"(a[1]), "r"(a[2]), "r"(a[3]), "r"(b[0]), "r"(b[1]));
}

__device__ __forceinline__ void ldsm_x4(uint32_t& r0, uint32_t& r1, uint32_t& r2,
                                        uint32_t& r3, uint32_t addr) {
    asm volatile("ldmatrix.sync.aligned.m8n8.x4.shared.b16 {%0,%1,%2,%3}, [%4];"
                 : "=r"(r0), "=r"(r1), "=r"(r2), "=r"(r3) : "r"(addr));
}

#define CP_ASYNC16(dst_u32, src_ptr, sz) \
    asm volatile("cp.async.cg.shared.global [%0], [%1], 16, %2;" \
        :: "r"(dst_u32), "l"(src_ptr), "r"(sz))
#define CP_COMMIT() asm volatile("cp.async.commit_group;" ::: "memory")
#define CP_WAIT1()  asm volatile("cp.async.wait_group 1;" ::: "memory")
#define CP_WAIT0()  asm volatile("cp.async.wait_group 0;" ::: "memory")

// ---------------- elementwise tf32 rounding pass ----------------
__global__ void round_pass_kernel(const float* __restrict__ in, float* __restrict__ out,
                                  int n4)
{
    const int stride = gridDim.x * blockDim.x;
    for (int i = blockIdx.x * blockDim.x + threadIdx.x; i < n4; i += stride) {
        float4 v = ((const float4*)in)[i];
        v.x = round_tf32(v.x); v.y = round_tf32(v.y);
        v.z = round_tf32(v.z); v.w = round_tf32(v.w);
        ((float4*)out)[i] = v;
    }
}

// ---------------- fused round + transpose: in[R][C] -> out[C][R] ----------------
__global__ void transpose_round_kernel(const float* __restrict__ in,
                                       float* __restrict__ out, int R, int C)
{
    __shared__ float tile[32][33];
    const int c0 = blockIdx.x * 32;
    const int r0 = blockIdx.y * 32;
    const int tx = threadIdx.x;
#pragma unroll
    for (int i = threadIdx.y; i < 32; i += 8)
        tile[i][tx] = round_tf32(in[(size_t)(r0 + i) * C + c0 + tx]);
    __syncthreads();
#pragma unroll
    for (int i = threadIdx.y; i < 32; i += 8)
        out[(size_t)(c0 + i) * R + r0 + tx] = tile[tx][i];
}

// ---------------- transpose v slice of kv into g_vt ----------------
__global__ void vtrans_kernel()
{
    __shared__ float tile[32][33];
    const int t0  = blockIdx.x * 32;
    const int dv0 = blockIdx.y * 32;
    const int h   = blockIdx.z;
    const int tx  = threadIdx.x;
#pragma unroll
    for (int i = threadIdx.y; i < 32; i += 8)
        tile[i][tx] = g_kv[(size_t)(t0 + i) * (NH * (DN + DV)) + h * (DN + DV) + DN + dv0 + tx];
    __syncthreads();
#pragma unroll
    for (int i = threadIdx.y; i < 32; i += 8)
        g_vt[(size_t)h * DV * T_TOK + (size_t)(dv0 + i) * T_TOK + t0 + tx] = tile[tx][i];
}

// ---------------- tensor-core tf32 GEMM: 3-stage cp.async multistage + ldmatrix ----------------
#define NSTAGE 3
#define STG_WORDS 8192
#define GEMM_SMEM_BYTES (2 * NSTAGE * STG_WORDS * 4)

template <bool SKIPN, bool CLAMPK, bool ROUNDC>
__global__ __launch_bounds__(256)
void tmma_gemm(const float* __restrict__ A, const float* __restrict__ B,
               float* __restrict__ C,
               int M, int N, int K, int lda, int ldb, int ldc,
               long long sA, long long sB, long long sC, float alpha)
{
    extern __shared__ float smf[];

    const int tid  = threadIdx.x;
    const int wid  = tid >> 5;
    const int lane = tid & 31;
    const int g    = lane >> 2;
    const int tig  = lane & 3;

    const int wm = (wid >> 1) * 32;
    const int wn = (wid & 1) * 64;

    const int z  = blockIdx.z;
    const int m0 = blockIdx.y * 128;
    const int n0 = blockIdx.x * 128;

    if (SKIPN && n0 > m0 + 127) return;

    A += (size_t)z * sA;
    B += (size_t)z * sB;
    C += (size_t)z * sC;

    int Keff = K;
    if (CLAMPK) Keff = min(K, m0 + 128);
    const int nkt = Keff >> 6;

    const uint32_t a_sm = (uint32_t)__cvta_generic_to_shared(smf);
    const uint32_t b_sm = a_sm + NSTAGE * STG_WORDS * 4;

    const int lrow = tid >> 4;
    const int lchk = tid & 15;

    auto load_tile = [&](int kt) {
        const int st = kt % NSTAGE;
        const int k0 = kt << 6;
        const uint32_t asb = a_sm + (uint32_t)st * STG_WORDS * 4;
        const uint32_t bsb = b_sm + (uint32_t)st * STG_WORDS * 4;
#pragma unroll
        for (int i = 0; i < 8; i++) {
            const int row = i * 16 + lrow;
            const uint32_t swz = (uint32_t)(lchk ^ (row & 7));
            const uint32_t dst = asb + (uint32_t)row * 256 + swz * 16;
            const float* src = A + (size_t)(m0 + row) * lda + k0 + lchk * 4;
            CP_ASYNC16(dst, src, 16);
        }
#pragma unroll
        for (int i = 0; i < 8; i++) {
            const int row = i * 16 + lrow;
            const bool in = (n0 + row < N);
            const uint32_t swz = (uint32_t)(lchk ^ (row & 7));
            const uint32_t dst = bsb + (uint32_t)row * 256 + swz * 16;
            const float* src = in ? (B + (size_t)(n0 + row) * ldb + k0 + lchk * 4) : B;
            CP_ASYNC16(dst, src, in ? 16 : 0);
        }
    };

    float acc[2][8][4];
#pragma unroll
    for (int mt = 0; mt < 2; mt++)
#pragma unroll
        for (int nt = 0; nt < 8; nt++)
#pragma unroll
            for (int r = 0; r < 4; r++) acc[mt][nt][r] = 0.0f;

    const int lr  = lane & 7;
    const int lhk = (lane >> 3) & 1;
    const int lhi = lane >> 4;

#pragma unroll
    for (int t = 0; t < NSTAGE - 1; t++) {
        if (t < nkt) load_tile(t);
        CP_COMMIT();
    }
    CP_WAIT1();
    __syncthreads();

    for (int kt = 0; kt < nkt; kt++) {
        if (kt + NSTAGE - 1 < nkt) load_tile(kt + NSTAGE - 1);
        CP_COMMIT();

        const int st = kt % NSTAGE;
        const uint32_t asb = a_sm + (uint32_t)st * STG_WORDS * 4;
        const uint32_t bsb = b_sm + (uint32_t)st * STG_WORDS * 4;

#pragma unroll
        for (int ks = 0; ks < 8; ks++) {
            uint32_t af[2][4];
#pragma unroll
            for (int mt = 0; mt < 2; mt++) {
                const int row = wm + mt * 16 + lhk * 8 + lr;
                const int chk = ks * 2 + lhi;
                const uint32_t addr = asb + (uint32_t)row * 256
                                    + (uint32_t)((chk ^ (row & 7)) * 16);
                ldsm_x4(af[mt][0], af[mt][1], af[mt][2], af[mt][3], addr);
            }
            uint32_t bf[8][2];
#pragma unroll
            for (int p = 0; p < 4; p++) {
                const int row = wn + p * 16 + lhi * 8 + lr;
                const int chk = ks * 2 + lhk;
                const uint32_t addr = bsb + (uint32_t)row * 256
                                    + (uint32_t)((chk ^ (row & 7)) * 16);
                ldsm_x4(bf[2 * p][0], bf[2 * p][1], bf[2 * p + 1][0], bf[2 * p + 1][1], addr);
            }
#pragma unroll
            for (int mt = 0; mt < 2; mt++)
#pragma unroll
                for (int nt = 0; nt < 8; nt++)
                    mma_tf32(acc[mt][nt], af[mt], bf[nt]);
        }

        CP_WAIT1();
        __syncthreads();
    }

#pragma unroll
    for (int mt = 0; mt < 2; mt++) {
#pragma unroll
        for (int nt = 0; nt < 8; nt++) {
            const int col = n0 + wn + nt * 8 + 2 * tig;
            if (col < N) {
                const int r0 = m0 + wm + mt * 16 + g;
                float o0 = alpha * acc[mt][nt][0], o1 = alpha * acc[mt][nt][1];
                float o2 = alpha * acc[mt][nt][2], o3 = alpha * acc[mt][nt][3];
                if (ROUNDC) {
                    o0 = round_tf32(o0); o1 = round_tf32(o1);
                    o2 = round_tf32(o2); o3 = round_tf32(o3);
                }
                *(float2*)&C[(size_t)r0 * ldc + col]       = make_float2(o0, o1);
                *(float2*)&C[(size_t)(r0 + 8) * ldc + col] = make_float2(o2, o3);
            }
        }
    }
}

// ---------------- fused online-softmax + PV + normalize (flash-style over g_s) ----------------
// Grid: (q-tile 16, head 32). Block 256 (8 warps, 4m x 2n), O acc 128x128.
// SMEM: P tile [128][128] (S in, rounded exp out, XOR-swizzled 16B chunks),
//       V double buffer 2x[128 dv][128 t], scale[128], lrec[128].
#define FLASH_P_BYTES   (128 * 128 * 4)
#define FLASH_V_BYTES   (128 * 128 * 4)
#define FLASH_SMEM_BYTES (FLASH_P_BYTES + 2 * FLASH_V_BYTES + 2 * 128 * 4)

__global__ __launch_bounds__(256)
void flash_pv_kernel()
{
    extern __shared__ float smf[];
    float* Pbuf  = smf;                                  // 128*128
    float* Vbuf  = smf + 128 * 128;                      // 2 x 128*128
    float* scale = smf + 3 * 128 * 128;                  // [128]
    float* lrec  = scale + 128;                          // [128]

    const int qt = blockIdx.x;          // q tile
    const int h  = blockIdx.y;          // head
    const int m0 = qt * 128;

    const int tid  = threadIdx.x;
    const int wid  = tid >> 5;
    const int lane = tid & 31;
    const int g    = lane >> 2;
    const int tig  = lane & 3;
    const int wm = (wid >> 1) * 32;
    const int wn = (wid & 1) * 64;

    const uint32_t p_sm = (uint32_t)__cvta_generic_to_shared(Pbuf);
    const uint32_t v_sm = (uint32_t)__cvta_generic_to_shared(Vbuf);

    const float* Sbase = g_s + (size_t)h * T_TOK * T_TOK;
    const float* Vtb   = g_vt + (size_t)h * DV * T_TOK;

    // loaders: tile [128 rows][32 chunks of 16B], swizzle chunk^(row&7) low bits
    auto load_S = [&](int jt) {
#pragma unroll
        for (int i = 0; i < 16; i++) {
            const int idx = i * 256 + tid;
            const int row = idx >> 5;
            const int chk = idx & 31;
            const uint32_t dst = p_sm + (uint32_t)row * 512
                               + (uint32_t)((chk ^ (row & 7)) << 4);
            const float* src = Sbase + (size_t)(m0 + row) * T_TOK + jt * 128 + chk * 4;
            CP_ASYNC16(dst, src, 16);
        }
    };
    auto load_V = [&](int jt) {
        const uint32_t vb = v_sm + (uint32_t)(jt & 1) * FLASH_V_BYTES;
#pragma unroll
        for (int i = 0; i < 16; i++) {
            const int idx = i * 256 + tid;
            const int row = idx >> 5;    // dv
            const int chk = idx & 31;
            const uint32_t dst = vb + (uint32_t)row * 512
                               + (uint32_t)((chk ^ (row & 7)) << 4);
            const float* src = Vtb + (size_t)row * T_TOK + jt * 128 + chk * 4;
            CP_ASYNC16(dst, src, 16);
        }
    };

    float acc[2][8][4];
#pragma unroll
    for (int mt = 0; mt < 2; mt++)
#pragma unroll
        for (int nt = 0; nt < 8; nt++)
#pragma unroll
            for (int r = 0; r < 4; r++) acc[mt][nt][r] = 0.0f;

    // softmax row ownership: 2 threads per row
    const int srow = tid >> 1;
    const int shalf = tid & 1;
    float m_run = -INFINITY;
    float l_run = 0.0f;

    const int lr  = lane & 7;
    const int lhk = (lane >> 3) & 1;
    const int lhi = lane >> 4;

    load_S(0);
    load_V(0);
    CP_COMMIT();
    CP_WAIT0();
    __syncthreads();

    for (int jt = 0; jt <= qt; jt++) {
        // ---- online softmax on S tile (in place -> P) ----
        {
            float* rp = Pbuf + srow * 128;
            const int r7 = srow & 7;
            const int jlim = (jt == qt) ? (srow + 1) : 128;  // causal (positions = arange)
            float tmax = -INFINITY;
            float vals[64];
#pragma unroll 16
            for (int j = 0; j < 64; j++) {
                const int col = shalf * 64 + j;
                float v = -INFINITY;
                if (col < jlim)
                    v = rp[(((col >> 2) ^ r7) << 2) + (col & 3)];
                vals[j] = v;
                tmax = fmaxf(tmax, v);
            }
            tmax = fmaxf(tmax, __shfl_xor_sync(0xFFFFFFFF, tmax, 1));
            const float newm = fmaxf(m_run, tmax);
            const float sc = __expf(m_run - newm);   // 0 when m_run=-inf
            float lsum = 0.0f;
#pragma unroll 16
            for (int j = 0; j < 64; j++) {
                const int col = shalf * 64 + j;
                float e = 0.0f;
                if (col < jlim) { e = __expf(vals[j] - newm); lsum += e; }
                rp[(((col >> 2) ^ r7) << 2) + (col & 3)] = round_tf32(e);
            }
            lsum += __shfl_xor_sync(0xFFFFFFFF, lsum, 1);
            l_run = l_run * sc + lsum;
            m_run = newm;
            if (shalf == 0) scale[srow] = sc;
        }
        __syncthreads();

        // prefetch next V under the MMA
        if (jt + 1 <= qt) { load_V(jt + 1); }
        CP_COMMIT();

        // ---- rescale O acc ----
#pragma unroll
        for (int mt = 0; mt < 2; mt++) {
            const int r0 = wm + mt * 16 + g;
            const float s0 = scale[r0];
            const float s1 = scale[r0 + 8];
#pragma unroll
            for (int nt = 0; nt < 8; nt++) {
                acc[mt][nt][0] *= s0; acc[mt][nt][1] *= s0;
                acc[mt][nt][2] *= s1; acc[mt][nt][3] *= s1;
            }
        }

        // ---- O += P @ V  (K = 128 -> 16 ks steps) ----
        const uint32_t vb = v_sm + (uint32_t)(jt & 1) * FLASH_V_BYTES;
#pragma unroll
        for (int ks = 0; ks < 16; ks++) {
            uint32_t af[2][4];
#pragma unroll
            for (int mt = 0; mt < 2; mt++) {
                const int row = wm + mt * 16 + lhk * 8 + lr;
                const int chk = ks * 2 + lhi;
                const uint32_t addr = p_sm + (uint32_t)row * 512
                                    + (uint32_t)((chk ^ (row & 7)) << 4);
                ldsm_x4(af[mt][0], af[mt][1], af[mt][2], af[mt][3], addr);
            }
            uint32_t bf[8][2];
#pragma unroll
            for (int p = 0; p < 4; p++) {
                const int row = wn + p * 16 + lhi * 8 + lr;
                const int chk = ks * 2 + lhk;
                const uint32_t addr = vb + (uint32_t)row * 512
                                    + (uint32_t)((chk ^ (row & 7)) << 4);
                ldsm_x4(bf[2 * p][0], bf[2 * p][1], bf[2 * p + 1][0], bf[2 * p + 1][1], addr);
            }
#pragma unroll
            for (int mt = 0; mt < 2; mt++)
#pragma unroll
                for (int nt = 0; nt < 8; nt++)
                    mma_tf32(acc[mt][nt], af[mt], bf[nt]);
        }
        __syncthreads();    // all warps done reading P

        if (jt + 1 <= qt) {
            load_S(jt + 1);
            CP_COMMIT();
            CP_WAIT0();     // S(jt+1) and V(jt+1) both ready
            __syncthreads();
        }
    }

    // ---- normalize + store attn (rounded, layout [t][h*DV+dv]) ----
    if (shalf == 0) lrec[srow] = 1.0f / l_run;
    __syncthreads();

#pragma unroll
    for (int mt = 0; mt < 2; mt++) {
        const int r0 = wm + mt * 16 + g;
        const float n0f = lrec[r0];
        const float n1f = lrec[r0 + 8];
#pragma unroll
        for (int nt = 0; nt < 8; nt++) {
            const int col = h * DV + wn + nt * 8 + 2 * tig;
            float o0 = round_tf32(acc[mt][nt][0] * n0f);
            float o1 = round_tf32(acc[mt][nt][1] * n0f);
            float o2 = round_tf32(acc[mt][nt][2] * n1f);
            float o3 = round_tf32(acc[mt][nt][3] * n1f);
            *(float2*)&g_attn[(size_t)(m0 + r0) * (NH * DV) + col]     = make_float2(o0, o1);
            *(float2*)&g_attn[(size_t)(m0 + r0 + 8) * (NH * DV) + col] = make_float2(o2, o3);
        }
    }
}

// ---------------- rmsnorm (writes tf32-rounded output) ----------------
__global__ void rmsnorm_kernel(float* __restrict__ x, const float* __restrict__ g,
                               int rowstride, int w)
{
    const int row = blockIdx.x;
    float* p = x + (size_t)row * rowstride;
    __shared__ float red[256];
    float s = 0.0f;
    for (int c = threadIdx.x; c < w; c += 256) { float v = p[c]; s += v * v; }
    red[threadIdx.x] = s;
    __syncthreads();
    for (int o = 128; o > 0; o >>= 1) {
        if (threadIdx.x < o) red[threadIdx.x] += red[threadIdx.x + o];
        __syncthreads();
    }
    const float r = rsqrtf(red[0] / (float)w + 1e-6f);
    for (int c = threadIdx.x; c < w; c += 256)
        p[c] = round_tf32(p[c] * r * g[c]);
}

// ---------------- interleaved RoPE ----------------
__global__ void rope_kernel(float* __restrict__ base, const int* __restrict__ positions,
                            int rowstride, int headstride, int offset, int round_nope)
{
    const int t = blockIdx.x;
    const int h = blockIdx.y;
    const int i = threadIdx.x;  // 0..31
    float* hp = base + (size_t)t * rowstride + h * headstride;
    float* p = hp + offset;
    const float pos = (float)positions[t];
    const float inv = powf(10000.0f, -(float)(2 * i) / 64.0f);
    float sn, cs;
    sincosf(pos * inv, &sn, &cs);
    const float x1 = p[2 * i];
    const float x2 = p[2 * i + 1];
    p[2 * i]     = round_tf32(x1 * cs - x2 * sn);
    p[2 * i + 1] = round_tf32(x1 * sn + x2 * cs);
    if (round_nope) {
#pragma unroll
        for (int j = 0; j < 4; j++)
            hp[i * 4 + j] = round_tf32(hp[i * 4 + j]);
    }
}

// ---------------- build k_full ----------------
__global__ void kfull_kernel()
{
    const int t = blockIdx.x;
    const int h = blockIdx.y;
    const int d = threadIdx.x;
    float v;
    if (d < DN) v = g_kv[(size_t)t * (NH * (DN + DV)) + h * (DN + DV) + d];
    else        v = g_kva[(size_t)t * (KVL + DR) + KVL + (d - DN)];
    g_kfull[(size_t)t * (NH * DH) + h * DH + d] = v;
}

// ---------------- launcher ----------------
extern "C" void kernel_launch(void* const* d_in, const int* in_sizes, int n_in,
                              void* d_out, int out_size)
{
    const int*   positions = (const int*)  d_in[0];
    const float* hidden    = (const float*)d_in[1];
    const float* wq_a      = (const float*)d_in[2];
    const float* gq        = (const float*)d_in[3];
    const float* wq_b      = (const float*)d_in[4];
    const float* wkv_a     = (const float*)d_in[5];
    const float* gkv       = (const float*)d_in[6];
    const float* wkv_b     = (const float*)d_in[7];
    const float* wo        = (const float*)d_in[8];
    float* out = (float*)d_out;

    float *qa, *q, *kva, *kv, *kfull, *s, *attn;
    float *hidr, *wqa, *wqb, *wkva, *wkvb, *wor;
    cudaGetSymbolAddress((void**)&qa,    g_qa);
    cudaGetSymbolAddress((void**)&q,     g_q);
    cudaGetSymbolAddress((void**)&kva,   g_kva);
    cudaGetSymbolAddress((void**)&kv,    g_kv);
    cudaGetSymbolAddress((void**)&kfull, g_kfull);
    cudaGetSymbolAddress((void**)&s,     g_s);
    cudaGetSymbolAddress((void**)&attn,  g_attn);
    cudaGetSymbolAddress((void**)&hidr,  g_hidr);
    cudaGetSymbolAddress((void**)&wqa,   g_wqa);
    cudaGetSymbolAddress((void**)&wqb,   g_wqb);
    cudaGetSymbolAddress((void**)&wkva,  g_wkva);
    cudaGetSymbolAddress((void**)&wkvb,  g_wkvb);
    cudaGetSymbolAddress((void**)&wor,   g_wo);

    static bool attr_done = false;
    if (!attr_done) {
        cudaFuncSetAttribute(tmma_gemm<false,false,false>,
            cudaFuncAttributeMaxDynamicSharedMemorySize, GEMM_SMEM_BYTES);
        cudaFuncSetAttribute(tmma_gemm<false,false,true>,
            cudaFuncAttributeMaxDynamicSharedMemorySize, GEMM_SMEM_BYTES);
        cudaFuncSetAttribute(tmma_gemm<true,false,false>,
            cudaFuncAttributeMaxDynamicSharedMemorySize, GEMM_SMEM_BYTES);
        cudaFuncSetAttribute(flash_pv_kernel,
            cudaFuncAttributeMaxDynamicSharedMemorySize, FLASH_SMEM_BYTES);
        attr_done = true;
    }

    const float scale = 1.0f / sqrtf((float)DH);
    const dim3 blk(256);
    const int  shm = GEMM_SMEM_BYTES;
    const dim3 tblk(32, 8);

    // 0. round hidden; round+transpose weights to [n][k]
    round_pass_kernel<<<1024, 256>>>(hidden, hidr, (int)((size_t)T_TOK * HID / 4));
    transpose_round_kernel<<<dim3(QL/32, HID/32), tblk>>>(wq_a, wqa, HID, QL);
    transpose_round_kernel<<<dim3(NH*DH/32, QL/32), tblk>>>(wq_b, wqb, QL, NH*DH);
    transpose_round_kernel<<<dim3((KVL+DR)/32, HID/32), tblk>>>(wkv_a, wkva, HID, KVL+DR);
    transpose_round_kernel<<<dim3(NH*(DN+DV)/32, KVL/32), tblk>>>(wkv_b, wkvb, KVL, NH*(DN+DV));
    transpose_round_kernel<<<dim3(HID/32, NH*DV/32), tblk>>>(wo, wor, NH*DV, HID);

    // 1. qa = hidr @ wqa^T           [2048,1536] K=4096
    tmma_gemm<false,false,false><<<dim3(QL/128, T_TOK/128, 1), blk, shm>>>(
        hidr, wqa, qa, T_TOK, QL, HID, HID, HID, QL, 0, 0, 0, 1.0f);

    // 2. rmsnorm(qa) -> rounded
    rmsnorm_kernel<<<T_TOK, 256>>>(qa, gq, QL, QL);

    // 3. q = qln @ wqb^T             [2048,6144] K=1536
    tmma_gemm<false,false,false><<<dim3(NH*DH/128, T_TOK/128, 1), blk, shm>>>(
        qa, wqb, q, T_TOK, NH*DH, QL, QL, QL, NH*DH, 0, 0, 0, 1.0f);

    // 4. kva = hidr @ wkva^T         [2048,576] K=4096
    tmma_gemm<false,false,false><<<dim3((KVL+DR+127)/128, T_TOK/128, 1), blk, shm>>>(
        hidr, wkva, kva, T_TOK, KVL+DR, HID, HID, HID, KVL+DR, 0, 0, 0, 1.0f);

    // 5. rmsnorm first 512 cols of kva -> rounded
    rmsnorm_kernel<<<T_TOK, 256>>>(kva, gkv, KVL+DR, KVL);

    // 6. kv = ckv_ln @ wkvb^T        [2048,8192] K=512  (epilogue rounds)
    tmma_gemm<false,false,true><<<dim3(NH*(DN+DV)/128, T_TOK/128, 1), blk, shm>>>(
        kva, wkvb, kv, T_TOK, NH*(DN+DV), KVL, KVL+DR, KVL, NH*(DN+DV),
        0, 0, 0, 1.0f);

    // 7. rope q_pe (+ round q_nope)
    rope_kernel<<<dim3(T_TOK, NH), 32>>>(q, positions, NH*DH, DH, DN, 1);

    // 8. rope k_pe
    rope_kernel<<<dim3(T_TOK, 1), 32>>>(kva, positions, KVL+DR, 0, KVL, 0);

    // 9. k_full + v^T
    kfull_kernel<<<dim3(T_TOK, NH), DH>>>();
    vtrans_kernel<<<dim3(T_TOK/32, DV/32, NH), tblk>>>();

    // 10. scores[h] = scale * q[h] @ kfull[h]^T   (causal tile skip)
    tmma_gemm<true,false,false><<<dim3(T_TOK/128, T_TOK/128, NH), blk, shm>>>(
        q, kfull, s, T_TOK, T_TOK, DH, NH*DH, NH*DH, T_TOK,
        (long long)DH, (long long)DH, (long long)T_TOK*T_TOK, scale);

    // 11. fused online softmax + PV + normalize
    flash_pv_kernel<<<dim3(T_TOK/128, NH), blk, FLASH_SMEM_BYTES>>>();

    // 12. out = attn @ wo^T           [2048,4096]
    tmma_gemm<false,false,false><<<dim3(HID/128, T_TOK/128, 1), blk, shm>>>(
        attn, wor, out, T_TOK, HID, NH*DV, NH*DV, NH*DV, HID, 0, 0, 0, 1.0f);
}

// round 9
// speedup vs baseline: 1.0790x; 1.0790x over previous
#include <cuda_runtime.h>
#include <cuda_bf16.h>
#include <math.h>
#include <stdint.h>

// ---------------- problem constants ----------------
#define T_TOK  2048
#define HID    4096
#define NH     32
#define DN     128   // qk_nope
#define DR     64    // qk_rope
#define DH     192   // qk_head
#define DV     128   // v_head
#define QL     1536  // q_lora
#define KVL    512   // kv_lora

// ---------------- device scratch ----------------
__device__ float g_qa    [(size_t)T_TOK * QL];
__device__ float g_q     [(size_t)T_TOK * NH * DH];
__device__ float g_kva   [(size_t)T_TOK * (KVL + DR)];
__device__ float g_kv    [(size_t)T_TOK * NH * (DN + DV)];
__device__ float g_kfull [(size_t)T_TOK * NH * DH];
__device__ float g_s     [(size_t)NH * T_TOK * T_TOK];
__device__ float g_attn  [(size_t)T_TOK * NH * DV];
__device__ float g_rowsum[(size_t)NH * T_TOK];
__device__ float g_vt    [(size_t)NH * DV * T_TOK];     // v transposed per head [h][dv][t]
// tf32-rounded (and transposed, for weights) copies of raw inputs
__device__ float g_hidr  [(size_t)T_TOK * HID];
__device__ float g_wqa   [(size_t)QL * HID];            // [n][k]
__device__ float g_wqb   [(size_t)NH * DH * QL];        // [n][k]
__device__ float g_wkva  [(size_t)(KVL + DR) * HID];    // [n][k]
__device__ float g_wkvb  [(size_t)NH * (DN + DV) * KVL];// [n][k]
__device__ float g_wo    [(size_t)HID * NH * DV];       // [n][k]

// ---------------- helpers ----------------
__device__ __forceinline__ float round_tf32(float x) {
    float y;
    asm("cvt.rna.tf32.f32 %0, %1;" : "=f"(y) : "f"(x));
    return y;
}

__device__ __forceinline__ void mma_tf32(float* c, const uint32_t* a, const uint32_t* b) {
    asm volatile(
        "mma.sync.aligned.m16n8k8.row.col.f32.tf32.tf32.f32 "
        "{%0,%1,%2,%3}, {%4,%5,%6,%7}, {%8,%9}, {%0,%1,%2,%3};"
        : "+f"(c[0]), "+f"(c[1]), "+f"(c[2]), "+f"(c[3])
        : "r"(a[0]), "r"(a[1]), "r"(a[2]), "r"(a[3]), "r"(b[0]), "r"(b[1]));
}

__device__ __forceinline__ void ldsm_x4(uint32_t& r0, uint32_t& r1, uint32_t& r2,
                                        uint32_t& r3, uint32_t addr) {
    asm volatile("ldmatrix.sync.aligned.m8n8.x4.shared.b16 {%0,%1,%2,%3}, [%4];"
                 : "=r"(r0), "=r"(r1), "=r"(r2), "=r"(r3) : "r"(addr));
}

#define CP_ASYNC16(dst_u32, src_ptr, sz) \
    asm volatile("cp.async.cg.shared.global [%0], [%1], 16, %2;" \
        :: "r"(dst_u32), "l"(src_ptr), "r"(sz))
#define CP_COMMIT() asm volatile("cp.async.commit_group;" ::: "memory")
#define CP_WAIT1()  asm volatile("cp.async.wait_group 1;" ::: "memory")
#define CP_WAIT0()  asm volatile("cp.async.wait_group 0;" ::: "memory")

// ---------------- elementwise tf32 rounding pass ----------------
__global__ void round_pass_kernel(const float* __restrict__ in, float* __restrict__ out,
                                  int n4)
{
    const int stride = gridDim.x * blockDim.x;
    for (int i = blockIdx.x * blockDim.x + threadIdx.x; i < n4; i += stride) {
        float4 v = ((const float4*)in)[i];
        v.x = round_tf32(v.x); v.y = round_tf32(v.y);
        v.z = round_tf32(v.z); v.w = round_tf32(v.w);
        ((float4*)out)[i] = v;
    }
}

// ---------------- fused round + transpose: in[R][C] -> out[C][R] ----------------
__global__ void transpose_round_kernel(const float* __restrict__ in,
                                       float* __restrict__ out, int R, int C)
{
    __shared__ float tile[32][33];
    const int c0 = blockIdx.x * 32;
    const int r0 = blockIdx.y * 32;
    const int tx = threadIdx.x;
#pragma unroll
    for (int i = threadIdx.y; i < 32; i += 8)
        tile[i][tx] = round_tf32(in[(size_t)(r0 + i) * C + c0 + tx]);
    __syncthreads();
#pragma unroll
    for (int i = threadIdx.y; i < 32; i += 8)
        out[(size_t)(c0 + i) * R + r0 + tx] = tile[tx][i];
}

// ---------------- transpose v slice of kv into g_vt ----------------
__global__ void vtrans_kernel()
{
    __shared__ float tile[32][33];
    const int t0  = blockIdx.x * 32;
    const int dv0 = blockIdx.y * 32;
    const int h   = blockIdx.z;
    const int tx  = threadIdx.x;
#pragma unroll
    for (int i = threadIdx.y; i < 32; i += 8)
        tile[i][tx] = g_kv[(size_t)(t0 + i) * (NH * (DN + DV)) + h * (DN + DV) + DN + dv0 + tx];
    __syncthreads();
#pragma unroll
    for (int i = threadIdx.y; i < 32; i += 8)
        g_vt[(size_t)h * DV * T_TOK + (size_t)(dv0 + i) * T_TOK + t0 + tx] = tile[tx][i];
}

// ---------------- tensor-core tf32 GEMM: BK=32, 3-stage cp.async, 2 CTAs/SM ----------------
// C[m,n] = alpha * sum_k A[m,k] * B[n,k]   (both operands K-major)
// BM=BN=128, BK=32, 256 threads (8 warps: 4m x 2n), warp tile 32x64.
// SMEM: XOR-swizzled (16B chunk ^ (row&7)). Stage = 128x32 floats = 16KB/operand.
// 3 stages x 2 operands = 96KB -> 2 CTAs/SM.
#define NSTAGE 3
#define STG_WORDS 4096
#define GEMM_SMEM_BYTES (2 * NSTAGE * STG_WORDS * 4)

template <bool SKIPN, bool CLAMPK, bool ROUNDC>
__global__ __launch_bounds__(256, 2)
void tmma_gemm(const float* __restrict__ A, const float* __restrict__ B,
               float* __restrict__ C,
               int M, int N, int K, int lda, int ldb, int ldc,
               long long sA, long long sB, long long sC, float alpha)
{
    extern __shared__ float smf[];

    const int tid  = threadIdx.x;
    const int wid  = tid >> 5;
    const int lane = tid & 31;
    const int g    = lane >> 2;
    const int tig  = lane & 3;

    const int wm = (wid >> 1) * 32;
    const int wn = (wid & 1) * 64;

    const int z  = blockIdx.z;
    const int m0 = blockIdx.y * 128;
    const int n0 = blockIdx.x * 128;

    if (SKIPN && n0 > m0 + 127) return;

    A += (size_t)z * sA;
    B += (size_t)z * sB;
    C += (size_t)z * sC;

    int Keff = K;
    if (CLAMPK) Keff = min(K, m0 + 128);
    const int nkt = Keff >> 5;

    const uint32_t a_sm = (uint32_t)__cvta_generic_to_shared(smf);
    const uint32_t b_sm = a_sm + NSTAGE * STG_WORDS * 4;

    // loader coords: 32 rows x 8 chunks per 256-thread pass
    const int lrow = tid >> 3;          // 0..31
    const int lchk = tid & 7;           // chunk 0..7

    auto load_tile = [&](int kt) {
        const int st = kt % NSTAGE;
        const int k0 = kt << 5;
        const uint32_t asb = a_sm + (uint32_t)st * STG_WORDS * 4;
        const uint32_t bsb = b_sm + (uint32_t)st * STG_WORDS * 4;
#pragma unroll
        for (int i = 0; i < 4; i++) {
            const int row = i * 32 + lrow;
            const uint32_t dst = asb + (uint32_t)row * 128
                               + (uint32_t)((lchk ^ (row & 7)) << 4);
            const float* src = A + (size_t)(m0 + row) * lda + k0 + lchk * 4;
            CP_ASYNC16(dst, src, 16);
        }
#pragma unroll
        for (int i = 0; i < 4; i++) {
            const int row = i * 32 + lrow;
            const bool in = (n0 + row < N);
            const uint32_t dst = bsb + (uint32_t)row * 128
                               + (uint32_t)((lchk ^ (row & 7)) << 4);
            const float* src = in ? (B + (size_t)(n0 + row) * ldb + k0 + lchk * 4) : B;
            CP_ASYNC16(dst, src, in ? 16 : 0);
        }
    };

    float acc[2][8][4];
#pragma unroll
    for (int mt = 0; mt < 2; mt++)
#pragma unroll
        for (int nt = 0; nt < 8; nt++)
#pragma unroll
            for (int r = 0; r < 4; r++) acc[mt][nt][r] = 0.0f;

    const int lr  = lane & 7;
    const int lhk = (lane >> 3) & 1;
    const int lhi = lane >> 4;

#pragma unroll
    for (int t = 0; t < NSTAGE - 1; t++) {
        if (t < nkt) load_tile(t);
        CP_COMMIT();
    }
    CP_WAIT1();
    __syncthreads();

    for (int kt = 0; kt < nkt; kt++) {
        if (kt + NSTAGE - 1 < nkt) load_tile(kt + NSTAGE - 1);
        CP_COMMIT();

        const int st = kt % NSTAGE;
        const uint32_t asb = a_sm + (uint32_t)st * STG_WORDS * 4;
        const uint32_t bsb = b_sm + (uint32_t)st * STG_WORDS * 4;

#pragma unroll
        for (int ks = 0; ks < 4; ks++) {
            uint32_t af[2][4];
#pragma unroll
            for (int mt = 0; mt < 2; mt++) {
                const int row = wm + mt * 16 + lhk * 8 + lr;
                const int chk = ks * 2 + lhi;
                const uint32_t addr = asb + (uint32_t)row * 128
                                    + (uint32_t)((chk ^ (row & 7)) << 4);
                ldsm_x4(af[mt][0], af[mt][1], af[mt][2], af[mt][3], addr);
            }
            uint32_t bf[8][2];
#pragma unroll
            for (int p = 0; p < 4; p++) {
                const int row = wn + p * 16 + lhi * 8 + lr;
                const int chk = ks * 2 + lhk;
                const uint32_t addr = bsb + (uint32_t)row * 128
                                    + (uint32_t)((chk ^ (row & 7)) << 4);
                ldsm_x4(bf[2 * p][0], bf[2 * p][1], bf[2 * p + 1][0], bf[2 * p + 1][1], addr);
            }
#pragma unroll
            for (int mt = 0; mt < 2; mt++)
#pragma unroll
                for (int nt = 0; nt < 8; nt++)
                    mma_tf32(acc[mt][nt], af[mt], bf[nt]);
        }

        CP_WAIT1();
        __syncthreads();
    }

    // ---- epilogue ----
#pragma unroll
    for (int mt = 0; mt < 2; mt++) {
#pragma unroll
        for (int nt = 0; nt < 8; nt++) {
            const int col = n0 + wn + nt * 8 + 2 * tig;
            if (col < N) {
                const int r0 = m0 + wm + mt * 16 + g;
                float o0 = alpha * acc[mt][nt][0], o1 = alpha * acc[mt][nt][1];
                float o2 = alpha * acc[mt][nt][2], o3 = alpha * acc[mt][nt][3];
                if (ROUNDC) {
                    o0 = round_tf32(o0); o1 = round_tf32(o1);
                    o2 = round_tf32(o2); o3 = round_tf32(o3);
                }
                *(float2*)&C[(size_t)r0 * ldc + col]       = make_float2(o0, o1);
                *(float2*)&C[(size_t)(r0 + 8) * ldc + col] = make_float2(o2, o3);
            }
        }
    }
}

// ---------------- rmsnorm (writes tf32-rounded output) ----------------
__global__ void rmsnorm_kernel(float* __restrict__ x, const float* __restrict__ g,
                               int rowstride, int w)
{
    const int row = blockIdx.x;
    float* p = x + (size_t)row * rowstride;
    __shared__ float red[256];
    float s = 0.0f;
    for (int c = threadIdx.x; c < w; c += 256) { float v = p[c]; s += v * v; }
    red[threadIdx.x] = s;
    __syncthreads();
    for (int o = 128; o > 0; o >>= 1) {
        if (threadIdx.x < o) red[threadIdx.x] += red[threadIdx.x + o];
        __syncthreads();
    }
    const float r = rsqrtf(red[0] / (float)w + 1e-6f);
    for (int c = threadIdx.x; c < w; c += 256)
        p[c] = round_tf32(p[c] * r * g[c]);
}

// ---------------- interleaved RoPE ----------------
__global__ void rope_kernel(float* __restrict__ base, const int* __restrict__ positions,
                            int rowstride, int headstride, int offset, int round_nope)
{
    const int t = blockIdx.x;
    const int h = blockIdx.y;
    const int i = threadIdx.x;  // 0..31
    float* hp = base + (size_t)t * rowstride + h * headstride;
    float* p = hp + offset;
    const float pos = (float)positions[t];
    const float inv = powf(10000.0f, -(float)(2 * i) / 64.0f);
    float sn, cs;
    sincosf(pos * inv, &sn, &cs);
    const float x1 = p[2 * i];
    const float x2 = p[2 * i + 1];
    p[2 * i]     = round_tf32(x1 * cs - x2 * sn);
    p[2 * i + 1] = round_tf32(x1 * sn + x2 * cs);
    if (round_nope) {
#pragma unroll
        for (int j = 0; j < 4; j++)
            hp[i * 4 + j] = round_tf32(hp[i * 4 + j]);
    }
}

// ---------------- build k_full ----------------
__global__ void kfull_kernel()
{
    const int t = blockIdx.x;
    const int h = blockIdx.y;
    const int d = threadIdx.x;
    float v;
    if (d < DN) v = g_kv[(size_t)t * (NH * (DN + DV)) + h * (DN + DV) + d];
    else        v = g_kva[(size_t)t * (KVL + DR) + KVL + (d - DN)];
    g_kfull[(size_t)t * (NH * DH) + h * DH + d] = v;
}

// ---------------- causal softmax: stores rounded exp, sums unrounded ----------------
__global__ void softmax_kernel(const int* __restrict__ positions)
{
    const int q = blockIdx.x;
    const int h = blockIdx.y;
    float* row = g_s + ((size_t)h * T_TOK + q) * T_TOK;
    const int pq = positions[q];
    const int jmax = ((q >> 7) + 1) << 7;
    __shared__ float red[256];
    const int tid = threadIdx.x;

    float m = -INFINITY;
    for (int j = tid; j < jmax; j += 256)
        if (positions[j] <= pq) m = fmaxf(m, row[j]);
    red[tid] = m;
    __syncthreads();
    for (int o = 128; o > 0; o >>= 1) {
        if (tid < o) red[tid] = fmaxf(red[tid], red[tid + o]);
        __syncthreads();
    }
    m = red[0];
    __syncthreads();

    float s = 0.0f;
    for (int j = tid; j < jmax; j += 256) {
        float v = 0.0f;
        if (positions[j] <= pq) { v = __expf(row[j] - m); s += v; }
        row[j] = round_tf32(v);
    }
    red[tid] = s;
    __syncthreads();
    for (int o = 128; o > 0; o >>= 1) {
        if (tid < o) red[tid] += red[tid + o];
        __syncthreads();
    }
    if (tid == 0) g_rowsum[(size_t)h * T_TOK + q] = red[0];
}

// ---------------- normalize attn rows (writes rounded) ----------------
__global__ void attn_norm_kernel()
{
    const int t = blockIdx.x;
    float* p = g_attn + (size_t)t * (NH * DV);
    for (int c = threadIdx.x; c < NH * DV; c += 256) {
        const int h = c >> 7;
        p[c] = round_tf32(p[c] * (1.0f / g_rowsum[(size_t)h * T_TOK + t]));
    }
}

// ---------------- launcher ----------------
extern "C" void kernel_launch(void* const* d_in, const int* in_sizes, int n_in,
                              void* d_out, int out_size)
{
    const int*   positions = (const int*)  d_in[0];
    const float* hidden    = (const float*)d_in[1];
    const float* wq_a      = (const float*)d_in[2];
    const float* gq        = (const float*)d_in[3];
    const float* wq_b      = (const float*)d_in[4];
    const float* wkv_a     = (const float*)d_in[5];
    const float* gkv       = (const float*)d_in[6];
    const float* wkv_b     = (const float*)d_in[7];
    const float* wo        = (const float*)d_in[8];
    float* out = (float*)d_out;

    float *qa, *q, *kva, *kv, *kfull, *s, *attn, *vt;
    float *hidr, *wqa, *wqb, *wkva, *wkvb, *wor;
    cudaGetSymbolAddress((void**)&qa,    g_qa);
    cudaGetSymbolAddress((void**)&q,     g_q);
    cudaGetSymbolAddress((void**)&kva,   g_kva);
    cudaGetSymbolAddress((void**)&kv,    g_kv);
    cudaGetSymbolAddress((void**)&kfull, g_kfull);
    cudaGetSymbolAddress((void**)&s,     g_s);
    cudaGetSymbolAddress((void**)&attn,  g_attn);
    cudaGetSymbolAddress((void**)&vt,    g_vt);
    cudaGetSymbolAddress((void**)&hidr,  g_hidr);
    cudaGetSymbolAddress((void**)&wqa,   g_wqa);
    cudaGetSymbolAddress((void**)&wqb,   g_wqb);
    cudaGetSymbolAddress((void**)&wkva,  g_wkva);
    cudaGetSymbolAddress((void**)&wkvb,  g_wkvb);
    cudaGetSymbolAddress((void**)&wor,   g_wo);

    static bool attr_done = false;
    if (!attr_done) {
        cudaFuncSetAttribute(tmma_gemm<false,false,false>,
            cudaFuncAttributeMaxDynamicSharedMemorySize, GEMM_SMEM_BYTES);
        cudaFuncSetAttribute(tmma_gemm<false,false,true>,
            cudaFuncAttributeMaxDynamicSharedMemorySize, GEMM_SMEM_BYTES);
        cudaFuncSetAttribute(tmma_gemm<true,false,false>,
            cudaFuncAttributeMaxDynamicSharedMemorySize, GEMM_SMEM_BYTES);
        cudaFuncSetAttribute(tmma_gemm<false,true,false>,
            cudaFuncAttributeMaxDynamicSharedMemorySize, GEMM_SMEM_BYTES);
        attr_done = true;
    }

    const float scale = 1.0f / sqrtf((float)DH);
    const dim3 blk(256);
    const int  shm = GEMM_SMEM_BYTES;
    const dim3 tblk(32, 8);

    // 0. round hidden; round+transpose weights to [n][k]
    round_pass_kernel<<<1024, 256>>>(hidden, hidr, (int)((size_t)T_TOK * HID / 4));
    transpose_round_kernel<<<dim3(QL/32, HID/32), tblk>>>(wq_a, wqa, HID, QL);
    transpose_round_kernel<<<dim3(NH*DH/32, QL/32), tblk>>>(wq_b, wqb, QL, NH*DH);
    transpose_round_kernel<<<dim3((KVL+DR)/32, HID/32), tblk>>>(wkv_a, wkva, HID, KVL+DR);
    transpose_round_kernel<<<dim3(NH*(DN+DV)/32, KVL/32), tblk>>>(wkv_b, wkvb, KVL, NH*(DN+DV));
    transpose_round_kernel<<<dim3(HID/32, NH*DV/32), tblk>>>(wo, wor, NH*DV, HID);

    // 1. qa = hidr @ wqa^T           [2048,1536] K=4096
    tmma_gemm<false,false,false><<<dim3(QL/128, T_TOK/128, 1), blk, shm>>>(
        hidr, wqa, qa, T_TOK, QL, HID, HID, HID, QL, 0, 0, 0, 1.0f);

    // 2. rmsnorm(qa) -> rounded
    rmsnorm_kernel<<<T_TOK, 256>>>(qa, gq, QL, QL);

    // 3. q = qln @ wqb^T             [2048,6144] K=1536
    tmma_gemm<false,false,false><<<dim3(NH*DH/128, T_TOK/128, 1), blk, shm>>>(
        qa, wqb, q, T_TOK, NH*DH, QL, QL, QL, NH*DH, 0, 0, 0, 1.0f);

    // 4. kva = hidr @ wkva^T         [2048,576] K=4096
    tmma_gemm<false,false,false><<<dim3((KVL+DR+127)/128, T_TOK/128, 1), blk, shm>>>(
        hidr, wkva, kva, T_TOK, KVL+DR, HID, HID, HID, KVL+DR, 0, 0, 0, 1.0f);

    // 5. rmsnorm first 512 cols of kva -> rounded
    rmsnorm_kernel<<<T_TOK, 256>>>(kva, gkv, KVL+DR, KVL);

    // 6. kv = ckv_ln @ wkvb^T        [2048,8192] K=512  (epilogue rounds)
    tmma_gemm<false,false,true><<<dim3(NH*(DN+DV)/128, T_TOK/128, 1), blk, shm>>>(
        kva, wkvb, kv, T_TOK, NH*(DN+DV), KVL, KVL+DR, KVL, NH*(DN+DV),
        0, 0, 0, 1.0f);

    // 7. rope q_pe (+ round q_nope)
    rope_kernel<<<dim3(T_TOK, NH), 32>>>(q, positions, NH*DH, DH, DN, 1);

    // 8. rope k_pe
    rope_kernel<<<dim3(T_TOK, 1), 32>>>(kva, positions, KVL+DR, 0, KVL, 0);

    // 9. k_full + v^T
    kfull_kernel<<<dim3(T_TOK, NH), DH>>>();
    vtrans_kernel<<<dim3(T_TOK/32, DV/32, NH), tblk>>>();

    // 10. scores[h] = scale * q[h] @ kfull[h]^T   (causal tile skip)
    tmma_gemm<true,false,false><<<dim3(T_TOK/128, T_TOK/128, NH), blk, shm>>>(
        q, kfull, s, T_TOK, T_TOK, DH, NH*DH, NH*DH, T_TOK,
        (long long)DH, (long long)DH, (long long)T_TOK*T_TOK, scale);

    // 11. causal softmax (stores rounded exp, sums fp32)
    softmax_kernel<<<dim3(T_TOK, NH), 256>>>(positions);

    // 12. attn[h] = exp_probs[h] @ vt[h]^T   (causal K clamp)
    tmma_gemm<false,true,false><<<dim3(1, T_TOK/128, NH), blk, shm>>>(
        s, vt, attn, T_TOK, DV, T_TOK, T_TOK, T_TOK, NH*DV,
        (long long)T_TOK*T_TOK, (long long)DV*T_TOK, (long long)DV, 1.0f);

    // 12b. normalize attn -> rounded
    attn_norm_kernel<<<T_TOK, 256>>>();

    // 13. out = attn @ wo^T           [2048,4096]
    tmma_gemm<false,false,false><<<dim3(HID/128, T_TOK/128, 1), blk, shm>>>(
        attn, wor, out, T_TOK, HID, NH*DV, NH*DV, NH*DV, HID, 0, 0, 0, 1.0f);
}

// round 10
// speedup vs baseline: 1.1552x; 1.0706x over previous
#include <cuda_runtime.h>
#include <cuda_bf16.h>
#include <math.h>
#include <stdint.h>

// ---------------- problem constants ----------------
#define T_TOK  2048
#define HID    4096
#define NH     32
#define DN     128   // qk_nope
#define DR     64    // qk_rope
#define DH     192   // qk_head
#define DV     128   // v_head
#define QL     1536  // q_lora
#define KVL    512   // kv_lora
#define QKV_N  (QL + KVL + DR)   // 2112 combined first-projection width

// ---------------- device scratch ----------------
__device__ float g_qakva [(size_t)T_TOK * QKV_N];       // [t][ qa(1536) | c_kv(512) | k_pe(64) ]
__device__ float g_q     [(size_t)T_TOK * NH * DH];
__device__ float g_kv    [(size_t)T_TOK * NH * (DN + DV)];
__device__ float g_kfull [(size_t)T_TOK * NH * DH];
__device__ float g_s     [(size_t)NH * T_TOK * T_TOK];
__device__ float g_attn  [(size_t)T_TOK * NH * DV];
__device__ float g_rowsum[(size_t)NH * T_TOK];
__device__ float g_vt    [(size_t)NH * DV * T_TOK];     // v transposed per head [h][dv][t]
// tf32-rounded (and transposed, for weights) copies of raw inputs
__device__ float g_hidr  [(size_t)T_TOK * HID];
__device__ float g_wqkva [(size_t)QKV_N * HID];         // [n][k]  rows: wqa | wkva
__device__ float g_wqb   [(size_t)NH * DH * QL];        // [n][k]
__device__ float g_wkvb  [(size_t)NH * (DN + DV) * KVL];// [n][k]
__device__ float g_wo    [(size_t)HID * NH * DV];       // [n][k]

// ---------------- helpers ----------------
__device__ __forceinline__ float round_tf32(float x) {
    float y;
    asm("cvt.rna.tf32.f32 %0, %1;" : "=f"(y) : "f"(x));
    return y;
}

__device__ __forceinline__ void mma_tf32(float* c, const uint32_t* a, const uint32_t* b) {
    asm volatile(
        "mma.sync.aligned.m16n8k8.row.col.f32.tf32.tf32.f32 "
        "{%0,%1,%2,%3}, {%4,%5,%6,%7}, {%8,%9}, {%0,%1,%2,%3};"
        : "+f"(c[0]), "+f"(c[1]), "+f"(c[2]), "+f"(c[3])
        : "r"(a[0]), "r"(a[1]), "r"(a[2]), "r"(a[3]), "r"(b[0]), "r"(b[1]));
}

__device__ __forceinline__ void ldsm_x4(uint32_t& r0, uint32_t& r1, uint32_t& r2,
                                        uint32_t& r3, uint32_t addr) {
    asm volatile("ldmatrix.sync.aligned.m8n8.x4.shared.b16 {%0,%1,%2,%3}, [%4];"
                 : "=r"(r0), "=r"(r1), "=r"(r2), "=r"(r3) : "r"(addr));
}

#define CP_ASYNC16(dst_u32, src_ptr, sz) \
    asm volatile("cp.async.cg.shared.global [%0], [%1], 16, %2;" \
        :: "r"(dst_u32), "l"(src_ptr), "r"(sz))
#define CP_COMMIT() asm volatile("cp.async.commit_group;" ::: "memory")
#define CP_WAIT1()  asm volatile("cp.async.wait_group 1;" ::: "memory")
#define CP_WAIT0()  asm volatile("cp.async.wait_group 0;" ::: "memory")

// ---------------- elementwise tf32 rounding pass ----------------
__global__ void round_pass_kernel(const float* __restrict__ in, float* __restrict__ out,
                                  int n4)
{
    const int stride = gridDim.x * blockDim.x;
    for (int i = blockIdx.x * blockDim.x + threadIdx.x; i < n4; i += stride) {
        float4 v = ((const float4*)in)[i];
        v.x = round_tf32(v.x); v.y = round_tf32(v.y);
        v.z = round_tf32(v.z); v.w = round_tf32(v.w);
        ((float4*)out)[i] = v;
    }
}

// ---------------- fused round + transpose: in[R][C] -> out[C][R] (out row offset) ----------------
__global__ void transpose_round_kernel(const float* __restrict__ in,
                                       float* __restrict__ out, int R, int C)
{
    __shared__ float tile[32][33];
    const int c0 = blockIdx.x * 32;
    const int r0 = blockIdx.y * 32;
    const int tx = threadIdx.x;
#pragma unroll
    for (int i = threadIdx.y; i < 32; i += 8)
        tile[i][tx] = round_tf32(in[(size_t)(r0 + i) * C + c0 + tx]);
    __syncthreads();
#pragma unroll
    for (int i = threadIdx.y; i < 32; i += 8)
        out[(size_t)(c0 + i) * R + r0 + tx] = tile[tx][i];
}

// ---------------- transpose v slice of kv into g_vt ----------------
__global__ void vtrans_kernel()
{
    __shared__ float tile[32][33];
    const int t0  = blockIdx.x * 32;
    const int dv0 = blockIdx.y * 32;
    const int h   = blockIdx.z;
    const int tx  = threadIdx.x;
#pragma unroll
    for (int i = threadIdx.y; i < 32; i += 8)
        tile[i][tx] = g_kv[(size_t)(t0 + i) * (NH * (DN + DV)) + h * (DN + DV) + DN + dv0 + tx];
    __syncthreads();
#pragma unroll
    for (int i = threadIdx.y; i < 32; i += 8)
        g_vt[(size_t)h * DV * T_TOK + (size_t)(dv0 + i) * T_TOK + t0 + tx] = tile[tx][i];
}

// ---------------- tensor-core tf32 GEMM: BK=32, 3-stage cp.async, 2 CTAs/SM ----------------
#define NSTAGE 3
#define STG_WORDS 4096
#define GEMM_SMEM_BYTES (2 * NSTAGE * STG_WORDS * 4)

template <bool SKIPN, bool CLAMPK, bool ROUNDC>
__global__ __launch_bounds__(256, 2)
void tmma_gemm(const float* __restrict__ A, const float* __restrict__ B,
               float* __restrict__ C,
               int M, int N, int K, int lda, int ldb, int ldc,
               long long sA, long long sB, long long sC, float alpha)
{
    extern __shared__ float smf[];

    const int tid  = threadIdx.x;
    const int wid  = tid >> 5;
    const int lane = tid & 31;
    const int g    = lane >> 2;
    const int tig  = lane & 3;

    const int wm = (wid >> 1) * 32;
    const int wn = (wid & 1) * 64;

    const int z  = blockIdx.z;
    const int m0 = blockIdx.y * 128;
    const int n0 = blockIdx.x * 128;

    if (SKIPN && n0 > m0 + 127) return;

    A += (size_t)z * sA;
    B += (size_t)z * sB;
    C += (size_t)z * sC;

    int Keff = K;
    if (CLAMPK) Keff = min(K, m0 + 128);
    const int nkt = Keff >> 5;

    const uint32_t a_sm = (uint32_t)__cvta_generic_to_shared(smf);
    const uint32_t b_sm = a_sm + NSTAGE * STG_WORDS * 4;

    const int lrow = tid >> 3;          // 0..31
    const int lchk = tid & 7;           // chunk 0..7

    auto load_tile = [&](int kt) {
        const int st = kt % NSTAGE;
        const int k0 = kt << 5;
        const uint32_t asb = a_sm + (uint32_t)st * STG_WORDS * 4;
        const uint32_t bsb = b_sm + (uint32_t)st * STG_WORDS * 4;
#pragma unroll
        for (int i = 0; i < 4; i++) {
            const int row = i * 32 + lrow;
            const uint32_t dst = asb + (uint32_t)row * 128
                               + (uint32_t)((lchk ^ (row & 7)) << 4);
            const float* src = A + (size_t)(m0 + row) * lda + k0 + lchk * 4;
            CP_ASYNC16(dst, src, 16);
        }
#pragma unroll
        for (int i = 0; i < 4; i++) {
            const int row = i * 32 + lrow;
            const bool in = (n0 + row < N);
            const uint32_t dst = bsb + (uint32_t)row * 128
                               + (uint32_t)((lchk ^ (row & 7)) << 4);
            const float* src = in ? (B + (size_t)(n0 + row) * ldb + k0 + lchk * 4) : B;
            CP_ASYNC16(dst, src, in ? 16 : 0);
        }
    };

    float acc[2][8][4];
#pragma unroll
    for (int mt = 0; mt < 2; mt++)
#pragma unroll
        for (int nt = 0; nt < 8; nt++)
#pragma unroll
            for (int r = 0; r < 4; r++) acc[mt][nt][r] = 0.0f;

    const int lr  = lane & 7;
    const int lhk = (lane >> 3) & 1;
    const int lhi = lane >> 4;

#pragma unroll
    for (int t = 0; t < NSTAGE - 1; t++) {
        if (t < nkt) load_tile(t);
        CP_COMMIT();
    }
    CP_WAIT1();
    __syncthreads();

    for (int kt = 0; kt < nkt; kt++) {
        if (kt + NSTAGE - 1 < nkt) load_tile(kt + NSTAGE - 1);
        CP_COMMIT();

        const int st = kt % NSTAGE;
        const uint32_t asb = a_sm + (uint32_t)st * STG_WORDS * 4;
        const uint32_t bsb = b_sm + (uint32_t)st * STG_WORDS * 4;

#pragma unroll
        for (int ks = 0; ks < 4; ks++) {
            uint32_t af[2][4];
#pragma unroll
            for (int mt = 0; mt < 2; mt++) {
                const int row = wm + mt * 16 + lhk * 8 + lr;
                const int chk = ks * 2 + lhi;
                const uint32_t addr = asb + (uint32_t)row * 128
                                    + (uint32_t)((chk ^ (row & 7)) << 4);
                ldsm_x4(af[mt][0], af[mt][1], af[mt][2], af[mt][3], addr);
            }
            uint32_t bf[8][2];
#pragma unroll
            for (int p = 0; p < 4; p++) {
                const int row = wn + p * 16 + lhi * 8 + lr;
                const int chk = ks * 2 + lhk;
                const uint32_t addr = bsb + (uint32_t)row * 128
                                    + (uint32_t)((chk ^ (row & 7)) << 4);
                ldsm_x4(bf[2 * p][0], bf[2 * p][1], bf[2 * p + 1][0], bf[2 * p + 1][1], addr);
            }
#pragma unroll
            for (int mt = 0; mt < 2; mt++)
#pragma unroll
                for (int nt = 0; nt < 8; nt++)
                    mma_tf32(acc[mt][nt], af[mt], bf[nt]);
        }

        CP_WAIT1();
        __syncthreads();
    }

    // ---- epilogue ----
#pragma unroll
    for (int mt = 0; mt < 2; mt++) {
#pragma unroll
        for (int nt = 0; nt < 8; nt++) {
            const int col = n0 + wn + nt * 8 + 2 * tig;
            if (col < N) {
                const int r0 = m0 + wm + mt * 16 + g;
                float o0 = alpha * acc[mt][nt][0], o1 = alpha * acc[mt][nt][1];
                float o2 = alpha * acc[mt][nt][2], o3 = alpha * acc[mt][nt][3];
                if (ROUNDC) {
                    o0 = round_tf32(o0); o1 = round_tf32(o1);
                    o2 = round_tf32(o2); o3 = round_tf32(o3);
                }
                *(float2*)&C[(size_t)r0 * ldc + col]       = make_float2(o0, o1);
                *(float2*)&C[(size_t)(r0 + 8) * ldc + col] = make_float2(o2, o3);
            }
        }
    }
}

// ---------------- fused dual rmsnorm over g_qakva (y=0: qa/QL, y=1: c_kv/KVL) ----------------
__global__ void rmsnorm2_kernel(const float* __restrict__ gq, const float* __restrict__ gkv)
{
    const int row = blockIdx.x;
    const int sec = blockIdx.y;
    const int off = sec ? QL : 0;
    const int w   = sec ? KVL : QL;
    const float* gg = sec ? gkv : gq;
    float* p = g_qakva + (size_t)row * QKV_N + off;
    __shared__ float red[256];
    float s = 0.0f;
    for (int c = threadIdx.x; c < w; c += 256) { float v = p[c]; s += v * v; }
    red[threadIdx.x] = s;
    __syncthreads();
    for (int o = 128; o > 0; o >>= 1) {
        if (threadIdx.x < o) red[threadIdx.x] += red[threadIdx.x + o];
        __syncthreads();
    }
    const float r = rsqrtf(red[0] / (float)w + 1e-6f);
    for (int c = threadIdx.x; c < w; c += 256)
        p[c] = round_tf32(p[c] * r * gg[c]);
}

// ---------------- fused RoPE: y<NH -> q head y (also rounds nope); y==NH -> k_pe ----------------
__global__ void rope_kernel(const int* __restrict__ positions)
{
    const int t = blockIdx.x;
    const int h = blockIdx.y;
    const int i = threadIdx.x;  // 0..31
    float* hp;
    float* p;
    if (h < NH) {
        hp = g_q + (size_t)t * (NH * DH) + h * DH;
        p  = hp + DN;
    } else {
        hp = nullptr;
        p  = g_qakva + (size_t)t * QKV_N + QL + KVL;
    }
    const float pos = (float)positions[t];
    const float inv = powf(10000.0f, -(float)(2 * i) / 64.0f);
    float sn, cs;
    sincosf(pos * inv, &sn, &cs);
    const float x1 = p[2 * i];
    const float x2 = p[2 * i + 1];
    p[2 * i]     = round_tf32(x1 * cs - x2 * sn);
    p[2 * i + 1] = round_tf32(x1 * sn + x2 * cs);
    if (h < NH) {
#pragma unroll
        for (int j = 0; j < 4; j++)
            hp[i * 4 + j] = round_tf32(hp[i * 4 + j]);
    }
}

// ---------------- build k_full ----------------
__global__ void kfull_kernel()
{
    const int t = blockIdx.x;
    const int h = blockIdx.y;
    const int d = threadIdx.x;
    float v;
    if (d < DN) v = g_kv[(size_t)t * (NH * (DN + DV)) + h * (DN + DV) + d];
    else        v = g_qakva[(size_t)t * QKV_N + QL + KVL + (d - DN)];
    g_kfull[(size_t)t * (NH * DH) + h * DH + d] = v;
}

// ---------------- causal softmax: stores rounded exp, sums unrounded ----------------
__global__ void softmax_kernel(const int* __restrict__ positions)
{
    const int q = blockIdx.x;
    const int h = blockIdx.y;
    float* row = g_s + ((size_t)h * T_TOK + q) * T_TOK;
    const int pq = positions[q];
    const int jmax = ((q >> 7) + 1) << 7;
    __shared__ float red[256];
    const int tid = threadIdx.x;

    float m = -INFINITY;
    for (int j = tid; j < jmax; j += 256)
        if (positions[j] <= pq) m = fmaxf(m, row[j]);
    red[tid] = m;
    __syncthreads();
    for (int o = 128; o > 0; o >>= 1) {
        if (tid < o) red[tid] = fmaxf(red[tid], red[tid + o]);
        __syncthreads();
    }
    m = red[0];
    __syncthreads();

    float s = 0.0f;
    for (int j = tid; j < jmax; j += 256) {
        float v = 0.0f;
        if (positions[j] <= pq) { v = __expf(row[j] - m); s += v; }
        row[j] = round_tf32(v);
    }
    red[tid] = s;
    __syncthreads();
    for (int o = 128; o > 0; o >>= 1) {
        if (tid < o) red[tid] += red[tid + o];
        __syncthreads();
    }
    if (tid == 0) g_rowsum[(size_t)h * T_TOK + q] = red[0];
}

// ---------------- normalize attn rows (writes rounded) ----------------
__global__ void attn_norm_kernel()
{
    const int t = blockIdx.x;
    float* p = g_attn + (size_t)t * (NH * DV);
    for (int c = threadIdx.x; c < NH * DV; c += 256) {
        const int h = c >> 7;
        p[c] = round_tf32(p[c] * (1.0f / g_rowsum[(size_t)h * T_TOK + t]));
    }
}

// ---------------- launcher ----------------
extern "C" void kernel_launch(void* const* d_in, const int* in_sizes, int n_in,
                              void* d_out, int out_size)
{
    const int*   positions = (const int*)  d_in[0];
    const float* hidden    = (const float*)d_in[1];
    const float* wq_a      = (const float*)d_in[2];
    const float* gq        = (const float*)d_in[3];
    const float* wq_b      = (const float*)d_in[4];
    const float* wkv_a     = (const float*)d_in[5];
    const float* gkv       = (const float*)d_in[6];
    const float* wkv_b     = (const float*)d_in[7];
    const float* wo        = (const float*)d_in[8];
    float* out = (float*)d_out;

    float *qakva, *q, *kv, *kfull, *s, *attn, *vt;
    float *hidr, *wqkva, *wqb, *wkvb, *wor;
    cudaGetSymbolAddress((void**)&qakva, g_qakva);
    cudaGetSymbolAddress((void**)&q,     g_q);
    cudaGetSymbolAddress((void**)&kv,    g_kv);
    cudaGetSymbolAddress((void**)&kfull, g_kfull);
    cudaGetSymbolAddress((void**)&s,     g_s);
    cudaGetSymbolAddress((void**)&attn,  g_attn);
    cudaGetSymbolAddress((void**)&vt,    g_vt);
    cudaGetSymbolAddress((void**)&hidr,  g_hidr);
    cudaGetSymbolAddress((void**)&wqkva, g_wqkva);
    cudaGetSymbolAddress((void**)&wqb,   g_wqb);
    cudaGetSymbolAddress((void**)&wkvb,  g_wkvb);
    cudaGetSymbolAddress((void**)&wor,   g_wo);

    static bool attr_done = false;
    if (!attr_done) {
        cudaFuncSetAttribute(tmma_gemm<false,false,false>,
            cudaFuncAttributeMaxDynamicSharedMemorySize, GEMM_SMEM_BYTES);
        cudaFuncSetAttribute(tmma_gemm<false,false,true>,
            cudaFuncAttributeMaxDynamicSharedMemorySize, GEMM_SMEM_BYTES);
        cudaFuncSetAttribute(tmma_gemm<true,false,false>,
            cudaFuncAttributeMaxDynamicSharedMemorySize, GEMM_SMEM_BYTES);
        cudaFuncSetAttribute(tmma_gemm<false,true,false>,
            cudaFuncAttributeMaxDynamicSharedMemorySize, GEMM_SMEM_BYTES);
        attr_done = true;
    }

    const float scale = 1.0f / sqrtf((float)DH);
    const dim3 blk(256);
    const int  shm = GEMM_SMEM_BYTES;
    const dim3 tblk(32, 8);

    // 0. round hidden; round+transpose weights ([n][k]; wqa & wkva into one buffer)
    round_pass_kernel<<<1024, 256>>>(hidden, hidr, (int)((size_t)T_TOK * HID / 4));
    transpose_round_kernel<<<dim3(QL/32, HID/32), tblk>>>(wq_a, wqkva, HID, QL);
    transpose_round_kernel<<<dim3((KVL+DR)/32, HID/32), tblk>>>(
        wkv_a, wqkva + (size_t)QL * HID, HID, KVL+DR);
    transpose_round_kernel<<<dim3(NH*DH/32, QL/32), tblk>>>(wq_b, wqb, QL, NH*DH);
    transpose_round_kernel<<<dim3(NH*(DN+DV)/32, KVL/32), tblk>>>(wkv_b, wkvb, KVL, NH*(DN+DV));
    transpose_round_kernel<<<dim3(HID/32, NH*DV/32), tblk>>>(wo, wor, NH*DV, HID);

    // 1. [qa | kva] = hidr @ wqkva^T   [2048,2112] K=4096 (one full wave)
    tmma_gemm<false,false,false><<<dim3((QKV_N+127)/128, T_TOK/128, 1), blk, shm>>>(
        hidr, wqkva, qakva, T_TOK, QKV_N, HID, HID, HID, QKV_N, 0, 0, 0, 1.0f);

    // 2. rmsnorm both sections -> rounded
    rmsnorm2_kernel<<<dim3(T_TOK, 2), 256>>>(gq, gkv);

    // 3. q = qa_ln @ wqb^T            [2048,6144] K=1536
    tmma_gemm<false,false,false><<<dim3(NH*DH/128, T_TOK/128, 1), blk, shm>>>(
        qakva, wqb, q, T_TOK, NH*DH, QL, QKV_N, QL, NH*DH, 0, 0, 0, 1.0f);

    // 4. kv = ckv_ln @ wkvb^T         [2048,8192] K=512  (epilogue rounds)
    tmma_gemm<false,false,true><<<dim3(NH*(DN+DV)/128, T_TOK/128, 1), blk, shm>>>(
        qakva + QL, wkvb, kv, T_TOK, NH*(DN+DV), KVL, QKV_N, KVL, NH*(DN+DV),
        0, 0, 0, 1.0f);

    // 5. rope q_pe (all heads, + round q_nope) and k_pe in one launch
    rope_kernel<<<dim3(T_TOK, NH + 1), 32>>>(positions);

    // 6. k_full + v^T
    kfull_kernel<<<dim3(T_TOK, NH), DH>>>();
    vtrans_kernel<<<dim3(T_TOK/32, DV/32, NH), tblk>>>();

    // 7. scores[h] = scale * q[h] @ kfull[h]^T   (causal tile skip)
    tmma_gemm<true,false,false><<<dim3(T_TOK/128, T_TOK/128, NH), blk, shm>>>(
        q, kfull, s, T_TOK, T_TOK, DH, NH*DH, NH*DH, T_TOK,
        (long long)DH, (long long)DH, (long long)T_TOK*T_TOK, scale);

    // 8. causal softmax (stores rounded exp, sums fp32)
    softmax_kernel<<<dim3(T_TOK, NH), 256>>>(positions);

    // 9. attn[h] = exp_probs[h] @ vt[h]^T   (causal K clamp)
    tmma_gemm<false,true,false><<<dim3(1, T_TOK/128, NH), blk, shm>>>(
        s, vt, attn, T_TOK, DV, T_TOK, T_TOK, T_TOK, NH*DV,
        (long long)T_TOK*T_TOK, (long long)DV*T_TOK, (long long)DV, 1.0f);

    // 10. normalize attn -> rounded
    attn_norm_kernel<<<T_TOK, 256>>>();

    // 11. out = attn @ wo^T           [2048,4096]
    tmma_gemm<false,false,false><<<dim3(HID/128, T_TOK/128, 1), blk, shm>>>(
        attn, wor, out, T_TOK, HID, NH*DV, NH*DV, NH*DV, HID, 0, 0, 0, 1.0f);
}

// round 11
// speedup vs baseline: 1.1891x; 1.0293x over previous
#include <cuda_runtime.h>
#include <cuda_bf16.h>
#include <math.h>
#include <stdint.h>

// ---------------- problem constants ----------------
#define T_TOK  2048
#define HID    4096
#define NH     32
#define DN     128   // qk_nope
#define DR     64    // qk_rope
#define DH     192   // qk_head
#define DV     128   // v_head
#define QL     1536  // q_lora
#define KVL    512   // kv_lora
#define QKV_N  (QL + KVL + DR)   // 2112 combined first-projection width

// ---------------- device scratch ----------------
__device__ float g_qakva [(size_t)T_TOK * QKV_N];       // [t][ qa(1536) | c_kv(512) | k_pe(64) ]
__device__ float g_q     [(size_t)T_TOK * NH * DH];
__device__ float g_kv    [(size_t)T_TOK * NH * (DN + DV)];
__device__ float g_s     [(size_t)NH * T_TOK * T_TOK];
__device__ float g_attn  [(size_t)T_TOK * NH * DV];
__device__ float g_rowsum[(size_t)NH * T_TOK];
__device__ float g_vt    [(size_t)NH * DV * T_TOK];     // v transposed per head [h][dv][t]
// tf32-rounded (and transposed, for weights) copies of raw inputs
__device__ float g_hidr  [(size_t)T_TOK * HID];
__device__ float g_wqkva [(size_t)QKV_N * HID];         // [n][k]  rows: wqa | wkva
__device__ float g_wqb   [(size_t)NH * DH * QL];        // [n][k]
__device__ float g_wkvb  [(size_t)NH * (DN + DV) * KVL];// [n][k]
__device__ float g_wo    [(size_t)HID * NH * DV];       // [n][k]

// ---------------- helpers ----------------
__device__ __forceinline__ float round_tf32(float x) {
    float y;
    asm("cvt.rna.tf32.f32 %0, %1;" : "=f"(y) : "f"(x));
    return y;
}

__device__ __forceinline__ void mma_tf32(float* c, const uint32_t* a, const uint32_t* b) {
    asm volatile(
        "mma.sync.aligned.m16n8k8.row.col.f32.tf32.tf32.f32 "
        "{%0,%1,%2,%3}, {%4,%5,%6,%7}, {%8,%9}, {%0,%1,%2,%3};"
        : "+f"(c[0]), "+f"(c[1]), "+f"(c[2]), "+f"(c[3])
        : "r"(a[0]), "r"(a[1]), "r"(a[2]), "r"(a[3]), "r"(b[0]), "r"(b[1]));
}

__device__ __forceinline__ void ldsm_x4(uint32_t& r0, uint32_t& r1, uint32_t& r2,
                                        uint32_t& r3, uint32_t addr) {
    asm volatile("ldmatrix.sync.aligned.m8n8.x4.shared.b16 {%0,%1,%2,%3}, [%4];"
                 : "=r"(r0), "=r"(r1), "=r"(r2), "=r"(r3) : "r"(addr));
}

#define CP_ASYNC16(dst_u32, src_ptr, sz) \
    asm volatile("cp.async.cg.shared.global [%0], [%1], 16, %2;" \
        :: "r"(dst_u32), "l"(src_ptr), "r"(sz))
#define CP_COMMIT() asm volatile("cp.async.commit_group;" ::: "memory")
#define CP_WAIT1()  asm volatile("cp.async.wait_group 1;" ::: "memory")
#define CP_WAIT0()  asm volatile("cp.async.wait_group 0;" ::: "memory")

// ---------------- elementwise tf32 rounding pass ----------------
__global__ void round_pass_kernel(const float* __restrict__ in, float* __restrict__ out,
                                  int n4)
{
    const int stride = gridDim.x * blockDim.x;
    for (int i = blockIdx.x * blockDim.x + threadIdx.x; i < n4; i += stride) {
        float4 v = ((const float4*)in)[i];
        v.x = round_tf32(v.x); v.y = round_tf32(v.y);
        v.z = round_tf32(v.z); v.w = round_tf32(v.w);
        ((float4*)out)[i] = v;
    }
}

// ---------------- fused round + transpose: in[R][C] -> out[C][R] ----------------
__global__ void transpose_round_kernel(const float* __restrict__ in,
                                       float* __restrict__ out, int R, int C)
{
    __shared__ float tile[32][33];
    const int c0 = blockIdx.x * 32;
    const int r0 = blockIdx.y * 32;
    const int tx = threadIdx.x;
#pragma unroll
    for (int i = threadIdx.y; i < 32; i += 8)
        tile[i][tx] = round_tf32(in[(size_t)(r0 + i) * C + c0 + tx]);
    __syncthreads();
#pragma unroll
    for (int i = threadIdx.y; i < 32; i += 8)
        out[(size_t)(c0 + i) * R + r0 + tx] = tile[tx][i];
}

// ---------------- transpose v slice of kv into g_vt ----------------
__global__ void vtrans_kernel()
{
    __shared__ float tile[32][33];
    const int t0  = blockIdx.x * 32;
    const int dv0 = blockIdx.y * 32;
    const int h   = blockIdx.z;
    const int tx  = threadIdx.x;
#pragma unroll
    for (int i = threadIdx.y; i < 32; i += 8)
        tile[i][tx] = g_kv[(size_t)(t0 + i) * (NH * (DN + DV)) + h * (DN + DV) + DN + dv0 + tx];
    __syncthreads();
#pragma unroll
    for (int i = threadIdx.y; i < 32; i += 8)
        g_vt[(size_t)h * DV * T_TOK + (size_t)(dv0 + i) * T_TOK + t0 + tx] = tile[tx][i];
}

// ---------------- tensor-core tf32 GEMM: BK=32, 3-stage cp.async, 2 CTAs/SM ----------------
// C[m,n] = alpha * sum_k A[m,k] * B[n,k]   (both operands K-major)
// DUALB: k-tiles with k0 >= KSPLIT(128) stream B rows from B2/ldb2 instead.
#define NSTAGE 3
#define STG_WORDS 4096
#define GEMM_SMEM_BYTES (2 * NSTAGE * STG_WORDS * 4)
#define KSPLIT 128

template <bool SKIPN, bool CLAMPK, bool ROUNDC, bool DUALB>
__global__ __launch_bounds__(256, 2)
void tmma_gemm(const float* __restrict__ A, const float* __restrict__ B,
               float* __restrict__ C,
               int M, int N, int K, int lda, int ldb, int ldc,
               long long sA, long long sB, long long sC, float alpha,
               const float* __restrict__ B2, int ldb2, long long sB2)
{
    extern __shared__ float smf[];

    const int tid  = threadIdx.x;
    const int wid  = tid >> 5;
    const int lane = tid & 31;
    const int g    = lane >> 2;
    const int tig  = lane & 3;

    const int wm = (wid >> 1) * 32;
    const int wn = (wid & 1) * 64;

    const int z  = blockIdx.z;
    const int m0 = blockIdx.y * 128;
    const int n0 = blockIdx.x * 128;

    if (SKIPN && n0 > m0 + 127) return;

    A += (size_t)z * sA;
    B += (size_t)z * sB;
    C += (size_t)z * sC;
    if (DUALB) B2 += (size_t)z * sB2;

    int Keff = K;
    if (CLAMPK) Keff = min(K, m0 + 128);
    const int nkt = Keff >> 5;

    const uint32_t a_sm = (uint32_t)__cvta_generic_to_shared(smf);
    const uint32_t b_sm = a_sm + NSTAGE * STG_WORDS * 4;

    const int lrow = tid >> 3;          // 0..31
    const int lchk = tid & 7;           // chunk 0..7

    auto load_tile = [&](int kt) {
        const int st = kt % NSTAGE;
        const int k0 = kt << 5;
        const uint32_t asb = a_sm + (uint32_t)st * STG_WORDS * 4;
        const uint32_t bsb = b_sm + (uint32_t)st * STG_WORDS * 4;
#pragma unroll
        for (int i = 0; i < 4; i++) {
            const int row = i * 32 + lrow;
            const uint32_t dst = asb + (uint32_t)row * 128
                               + (uint32_t)((lchk ^ (row & 7)) << 4);
            const float* src = A + (size_t)(m0 + row) * lda + k0 + lchk * 4;
            CP_ASYNC16(dst, src, 16);
        }
        const float* Bp = B;
        int koff = k0, ldbp = ldb;
        if (DUALB && k0 >= KSPLIT) { Bp = B2; koff = k0 - KSPLIT; ldbp = ldb2; }
#pragma unroll
        for (int i = 0; i < 4; i++) {
            const int row = i * 32 + lrow;
            const bool in = (n0 + row < N);
            const uint32_t dst = bsb + (uint32_t)row * 128
                               + (uint32_t)((lchk ^ (row & 7)) << 4);
            const float* src = in ? (Bp + (size_t)(n0 + row) * ldbp + koff + lchk * 4) : Bp;
            CP_ASYNC16(dst, src, in ? 16 : 0);
        }
    };

    float acc[2][8][4];
#pragma unroll
    for (int mt = 0; mt < 2; mt++)
#pragma unroll
        for (int nt = 0; nt < 8; nt++)
#pragma unroll
            for (int r = 0; r < 4; r++) acc[mt][nt][r] = 0.0f;

    const int lr  = lane & 7;
    const int lhk = (lane >> 3) & 1;
    const int lhi = lane >> 4;

#pragma unroll
    for (int t = 0; t < NSTAGE - 1; t++) {
        if (t < nkt) load_tile(t);
        CP_COMMIT();
    }
    CP_WAIT1();
    __syncthreads();

    for (int kt = 0; kt < nkt; kt++) {
        if (kt + NSTAGE - 1 < nkt) load_tile(kt + NSTAGE - 1);
        CP_COMMIT();

        const int st = kt % NSTAGE;
        const uint32_t asb = a_sm + (uint32_t)st * STG_WORDS * 4;
        const uint32_t bsb = b_sm + (uint32_t)st * STG_WORDS * 4;

#pragma unroll
        for (int ks = 0; ks < 4; ks++) {
            uint32_t af[2][4];
#pragma unroll
            for (int mt = 0; mt < 2; mt++) {
                const int row = wm + mt * 16 + lhk * 8 + lr;
                const int chk = ks * 2 + lhi;
                const uint32_t addr = asb + (uint32_t)row * 128
                                    + (uint32_t)((chk ^ (row & 7)) << 4);
                ldsm_x4(af[mt][0], af[mt][1], af[mt][2], af[mt][3], addr);
            }
            uint32_t bf[8][2];
#pragma unroll
            for (int p = 0; p < 4; p++) {
                const int row = wn + p * 16 + lhi * 8 + lr;
                const int chk = ks * 2 + lhk;
                const uint32_t addr = bsb + (uint32_t)row * 128
                                    + (uint32_t)((chk ^ (row & 7)) << 4);
                ldsm_x4(bf[2 * p][0], bf[2 * p][1], bf[2 * p + 1][0], bf[2 * p + 1][1], addr);
            }
#pragma unroll
            for (int mt = 0; mt < 2; mt++)
#pragma unroll
                for (int nt = 0; nt < 8; nt++)
                    mma_tf32(acc[mt][nt], af[mt], bf[nt]);
        }

        CP_WAIT1();
        __syncthreads();
    }

    // ---- epilogue ----
#pragma unroll
    for (int mt = 0; mt < 2; mt++) {
#pragma unroll
        for (int nt = 0; nt < 8; nt++) {
            const int col = n0 + wn + nt * 8 + 2 * tig;
            if (col < N) {
                const int r0 = m0 + wm + mt * 16 + g;
                float o0 = alpha * acc[mt][nt][0], o1 = alpha * acc[mt][nt][1];
                float o2 = alpha * acc[mt][nt][2], o3 = alpha * acc[mt][nt][3];
                if (ROUNDC) {
                    o0 = round_tf32(o0); o1 = round_tf32(o1);
                    o2 = round_tf32(o2); o3 = round_tf32(o3);
                }
                *(float2*)&C[(size_t)r0 * ldc + col]       = make_float2(o0, o1);
                *(float2*)&C[(size_t)(r0 + 8) * ldc + col] = make_float2(o2, o3);
            }
        }
    }
}

// ---------------- fused dual rmsnorm over g_qakva ----------------
__global__ void rmsnorm2_kernel(const float* __restrict__ gq, const float* __restrict__ gkv)
{
    const int row = blockIdx.x;
    const int sec = blockIdx.y;
    const int off = sec ? QL : 0;
    const int w   = sec ? KVL : QL;
    const float* gg = sec ? gkv : gq;
    float* p = g_qakva + (size_t)row * QKV_N + off;
    __shared__ float red[256];
    float s = 0.0f;
    for (int c = threadIdx.x; c < w; c += 256) { float v = p[c]; s += v * v; }
    red[threadIdx.x] = s;
    __syncthreads();
    for (int o = 128; o > 0; o >>= 1) {
        if (threadIdx.x < o) red[threadIdx.x] += red[threadIdx.x + o];
        __syncthreads();
    }
    const float r = rsqrtf(red[0] / (float)w + 1e-6f);
    for (int c = threadIdx.x; c < w; c += 256)
        p[c] = round_tf32(p[c] * r * gg[c]);
}

// ---------------- fused RoPE: y<NH -> q head y (+ round nope); y==NH -> k_pe ----------------
__global__ void rope_kernel(const int* __restrict__ positions)
{
    const int t = blockIdx.x;
    const int h = blockIdx.y;
    const int i = threadIdx.x;  // 0..31
    float* hp;
    float* p;
    if (h < NH) {
        hp = g_q + (size_t)t * (NH * DH) + h * DH;
        p  = hp + DN;
    } else {
        hp = nullptr;
        p  = g_qakva + (size_t)t * QKV_N + QL + KVL;
    }
    const float pos = (float)positions[t];
    const float inv = powf(10000.0f, -(float)(2 * i) / 64.0f);
    float sn, cs;
    sincosf(pos * inv, &sn, &cs);
    const float x1 = p[2 * i];
    const float x2 = p[2 * i + 1];
    p[2 * i]     = round_tf32(x1 * cs - x2 * sn);
    p[2 * i + 1] = round_tf32(x1 * sn + x2 * cs);
    if (h < NH) {
#pragma unroll
        for (int j = 0; j < 4; j++)
            hp[i * 4 + j] = round_tf32(hp[i * 4 + j]);
    }
}

// ---------------- single-pass causal softmax: registers cache the row ----------------
__global__ __launch_bounds__(256)
void softmax_kernel(const int* __restrict__ positions)
{
    const int q = blockIdx.x;
    const int h = blockIdx.y;
    float* row = g_s + ((size_t)h * T_TOK + q) * T_TOK;
    const int pq = positions[q];
    const int jmax = ((q >> 7) + 1) << 7;       // 128..2048
    __shared__ float red[256];
    const int tid = threadIdx.x;

    float vals[8];                               // jmax/256 <= 8 entries
    int cnt = 0;
    float m = -INFINITY;
    for (int j = tid; j < jmax; j += 256) {
        float v = (positions[j] <= pq) ? row[j] : -INFINITY;
        vals[cnt++] = v;
        m = fmaxf(m, v);
    }
    red[tid] = m;
    __syncthreads();
    for (int o = 128; o > 0; o >>= 1) {
        if (tid < o) red[tid] = fmaxf(red[tid], red[tid + o]);
        __syncthreads();
    }
    m = red[0];
    __syncthreads();

    float s = 0.0f;
    cnt = 0;
    for (int j = tid; j < jmax; j += 256) {
        const float e = __expf(vals[cnt++] - m);  // exp(-inf - m) = 0 exactly
        s += e;
        row[j] = round_tf32(e);
    }
    red[tid] = s;
    __syncthreads();
    for (int o = 128; o > 0; o >>= 1) {
        if (tid < o) red[tid] += red[tid + o];
        __syncthreads();
    }
    if (tid == 0) g_rowsum[(size_t)h * T_TOK + q] = red[0];
}

// ---------------- normalize attn rows (writes rounded) ----------------
__global__ void attn_norm_kernel()
{
    const int t = blockIdx.x;
    float* p = g_attn + (size_t)t * (NH * DV);
    for (int c = threadIdx.x; c < NH * DV; c += 256) {
        const int h = c >> 7;
        p[c] = round_tf32(p[c] * (1.0f / g_rowsum[(size_t)h * T_TOK + t]));
    }
}

// ---------------- launcher ----------------
extern "C" void kernel_launch(void* const* d_in, const int* in_sizes, int n_in,
                              void* d_out, int out_size)
{
    const int*   positions = (const int*)  d_in[0];
    const float* hidden    = (const float*)d_in[1];
    const float* wq_a      = (const float*)d_in[2];
    const float* gq        = (const float*)d_in[3];
    const float* wq_b      = (const float*)d_in[4];
    const float* wkv_a     = (const float*)d_in[5];
    const float* gkv       = (const float*)d_in[6];
    const float* wkv_b     = (const float*)d_in[7];
    const float* wo        = (const float*)d_in[8];
    float* out = (float*)d_out;

    float *qakva, *q, *kv, *s, *attn, *vt;
    float *hidr, *wqkva, *wqb, *wkvb, *wor;
    cudaGetSymbolAddress((void**)&qakva, g_qakva);
    cudaGetSymbolAddress((void**)&q,     g_q);
    cudaGetSymbolAddress((void**)&kv,    g_kv);
    cudaGetSymbolAddress((void**)&s,     g_s);
    cudaGetSymbolAddress((void**)&attn,  g_attn);
    cudaGetSymbolAddress((void**)&vt,    g_vt);
    cudaGetSymbolAddress((void**)&hidr,  g_hidr);
    cudaGetSymbolAddress((void**)&wqkva, g_wqkva);
    cudaGetSymbolAddress((void**)&wqb,   g_wqb);
    cudaGetSymbolAddress((void**)&wkvb,  g_wkvb);
    cudaGetSymbolAddress((void**)&wor,   g_wo);

    static bool attr_done = false;
    if (!attr_done) {
        cudaFuncSetAttribute(tmma_gemm<false,false,false,false>,
            cudaFuncAttributeMaxDynamicSharedMemorySize, GEMM_SMEM_BYTES);
        cudaFuncSetAttribute(tmma_gemm<false,false,true,false>,
            cudaFuncAttributeMaxDynamicSharedMemorySize, GEMM_SMEM_BYTES);
        cudaFuncSetAttribute(tmma_gemm<true,false,false,true>,
            cudaFuncAttributeMaxDynamicSharedMemorySize, GEMM_SMEM_BYTES);
        cudaFuncSetAttribute(tmma_gemm<false,true,false,false>,
            cudaFuncAttributeMaxDynamicSharedMemorySize, GEMM_SMEM_BYTES);
        attr_done = true;
    }

    const float scale = 1.0f / sqrtf((float)DH);
    const dim3 blk(256);
    const int  shm = GEMM_SMEM_BYTES;
    const dim3 tblk(32, 8);

    // 0. round hidden; round+transpose weights ([n][k]; wqa & wkva into one buffer)
    round_pass_kernel<<<1024, 256>>>(hidden, hidr, (int)((size_t)T_TOK * HID / 4));
    transpose_round_kernel<<<dim3(QL/32, HID/32), tblk>>>(wq_a, wqkva, HID, QL);
    transpose_round_kernel<<<dim3((KVL+DR)/32, HID/32), tblk>>>(
        wkv_a, wqkva + (size_t)QL * HID, HID, KVL+DR);
    transpose_round_kernel<<<dim3(NH*DH/32, QL/32), tblk>>>(wq_b, wqb, QL, NH*DH);
    transpose_round_kernel<<<dim3(NH*(DN+DV)/32, KVL/32), tblk>>>(wkv_b, wkvb, KVL, NH*(DN+DV));
    transpose_round_kernel<<<dim3(HID/32, NH*DV/32), tblk>>>(wo, wor, NH*DV, HID);

    // 1. [qa | kva] = hidr @ wqkva^T   [2048,2112] K=4096
    tmma_gemm<false,false,false,false><<<dim3((QKV_N+127)/128, T_TOK/128, 1), blk, shm>>>(
        hidr, wqkva, qakva, T_TOK, QKV_N, HID, HID, HID, QKV_N, 0, 0, 0, 1.0f,
        nullptr, 0, 0);

    // 2. rmsnorm both sections -> rounded
    rmsnorm2_kernel<<<dim3(T_TOK, 2), 256>>>(gq, gkv);

    // 3. q = qa_ln @ wqb^T            [2048,6144] K=1536
    tmma_gemm<false,false,false,false><<<dim3(NH*DH/128, T_TOK/128, 1), blk, shm>>>(
        qakva, wqb, q, T_TOK, NH*DH, QL, QKV_N, QL, NH*DH, 0, 0, 0, 1.0f,
        nullptr, 0, 0);

    // 4. kv = ckv_ln @ wkvb^T         [2048,8192] K=512  (epilogue rounds)
    tmma_gemm<false,false,true,false><<<dim3(NH*(DN+DV)/128, T_TOK/128, 1), blk, shm>>>(
        qakva + QL, wkvb, kv, T_TOK, NH*(DN+DV), KVL, QKV_N, KVL, NH*(DN+DV),
        0, 0, 0, 1.0f, nullptr, 0, 0);

    // 5. rope q_pe (all heads, + round q_nope) and k_pe in one launch
    rope_kernel<<<dim3(T_TOK, NH + 1), 32>>>(positions);

    // 6. v^T
    vtrans_kernel<<<dim3(T_TOK/32, DV/32, NH), tblk>>>();

    // 7. scores[h] = scale * q[h] @ [k_nope | k_pe]^T  (dual-source B, causal tile skip)
    tmma_gemm<true,false,false,true><<<dim3(T_TOK/128, T_TOK/128, NH), blk, shm>>>(
        q, kv, s, T_TOK, T_TOK, DH, NH*DH, NH*(DN+DV), T_TOK,
        (long long)DH, (long long)(DN+DV), (long long)T_TOK*T_TOK, scale,
        qakva + QL + KVL, QKV_N, 0);

    // 8. single-pass causal softmax (stores rounded exp, sums fp32)
    softmax_kernel<<<dim3(T_TOK, NH), 256>>>(positions);

    // 9. attn[h] = exp_probs[h] @ vt[h]^T   (causal K clamp)
    tmma_gemm<false,true,false,false><<<dim3(1, T_TOK/128, NH), blk, shm>>>(
        s, vt, attn, T_TOK, DV, T_TOK, T_TOK, T_TOK, NH*DV,
        (long long)T_TOK*T_TOK, (long long)DV*T_TOK, (long long)DV, 1.0f,
        nullptr, 0, 0);

    // 10. normalize attn -> rounded
    attn_norm_kernel<<<T_TOK, 256>>>();

    // 11. out = attn @ wo^T           [2048,4096]
    tmma_gemm<false,false,false,false><<<dim3(HID/128, T_TOK/128, 1), blk, shm>>>(
        attn, wor, out, T_TOK, HID, NH*DV, NH*DV, NH*DV, HID, 0, 0, 0, 1.0f,
        nullptr, 0, 0);
}

// round 12
// speedup vs baseline: 1.2350x; 1.0386x over previous
#include <cuda_runtime.h>
#include <cuda_bf16.h>
#include <math.h>
#include <stdint.h>

// ---------------- problem constants ----------------
#define T_TOK  2048
#define HID    4096
#define NH     32
#define DN     128   // qk_nope
#define DR     64    // qk_rope
#define DH     192   // qk_head
#define DV     128   // v_head
#define QL     1536  // q_lora
#define KVL    512   // kv_lora
#define QKV_N  (QL + KVL + DR)   // 2112 combined first-projection width

// ---------------- device scratch ----------------
__device__ float g_qakva [(size_t)T_TOK * QKV_N];       // [t][ qa(1536) | c_kv(512) | k_pe(64) ]
__device__ float g_q     [(size_t)T_TOK * NH * DH];
__device__ float g_kv    [(size_t)T_TOK * NH * (DN + DV)];
__device__ float g_s     [(size_t)NH * T_TOK * T_TOK];
__device__ float g_attn  [(size_t)T_TOK * NH * DV];
__device__ float g_rowsum[(size_t)NH * T_TOK];
__device__ float g_vt    [(size_t)NH * DV * T_TOK];     // v transposed per head [h][dv][t]
// tf32-rounded (and transposed, for weights) copies of raw inputs
__device__ float g_hidr  [(size_t)T_TOK * HID];
__device__ float g_wqkva [(size_t)QKV_N * HID];         // [n][k]  rows: wqa | wkva
__device__ float g_wqb   [(size_t)NH * DH * QL];        // [n][k]
__device__ float g_wkvb  [(size_t)NH * (DN + DV) * KVL];// [n][k]
__device__ float g_wo    [(size_t)HID * NH * DV];       // [n][k]

// ---------------- helpers ----------------
__device__ __forceinline__ float round_tf32(float x) {
    float y;
    asm("cvt.rna.tf32.f32 %0, %1;" : "=f"(y) : "f"(x));
    return y;
}

__device__ __forceinline__ void mma_tf32(float* c, const uint32_t* a, const uint32_t* b) {
    asm volatile(
        "mma.sync.aligned.m16n8k8.row.col.f32.tf32.tf32.f32 "
        "{%0,%1,%2,%3}, {%4,%5,%6,%7}, {%8,%9}, {%0,%1,%2,%3};"
        : "+f"(c[0]), "+f"(c[1]), "+f"(c[2]), "+f"(c[3])
        : "r"(a[0]), "r"(a[1]), "r"(a[2]), "r"(a[3]), "r"(b[0]), "r"(b[1]));
}

__device__ __forceinline__ void ldsm_x4(uint32_t& r0, uint32_t& r1, uint32_t& r2,
                                        uint32_t& r3, uint32_t addr) {
    asm volatile("ldmatrix.sync.aligned.m8n8.x4.shared.b16 {%0,%1,%2,%3}, [%4];"
                 : "=r"(r0), "=r"(r1), "=r"(r2), "=r"(r3) : "r"(addr));
}

#define CP_ASYNC16(dst_u32, src_ptr, sz) \
    asm volatile("cp.async.cg.shared.global [%0], [%1], 16, %2;" \
        :: "r"(dst_u32), "l"(src_ptr), "r"(sz))
#define CP_COMMIT() asm volatile("cp.async.commit_group;" ::: "memory")
#define CP_WAIT1()  asm volatile("cp.async.wait_group 1;" ::: "memory")
#define CP_WAIT0()  asm volatile("cp.async.wait_group 0;" ::: "memory")

// ---------------- elementwise tf32 rounding pass ----------------
__global__ void round_pass_kernel(const float* __restrict__ in, float* __restrict__ out,
                                  int n4)
{
    const int stride = gridDim.x * blockDim.x;
    for (int i = blockIdx.x * blockDim.x + threadIdx.x; i < n4; i += stride) {
        float4 v = ((const float4*)in)[i];
        v.x = round_tf32(v.x); v.y = round_tf32(v.y);
        v.z = round_tf32(v.z); v.w = round_tf32(v.w);
        ((float4*)out)[i] = v;
    }
}

// ---------------- fused round + transpose: in[R][C] -> out[C][R] ----------------
__global__ void transpose_round_kernel(const float* __restrict__ in,
                                       float* __restrict__ out, int R, int C)
{
    __shared__ float tile[32][33];
    const int c0 = blockIdx.x * 32;
    const int r0 = blockIdx.y * 32;
    const int tx = threadIdx.x;
#pragma unroll
    for (int i = threadIdx.y; i < 32; i += 8)
        tile[i][tx] = round_tf32(in[(size_t)(r0 + i) * C + c0 + tx]);
    __syncthreads();
#pragma unroll
    for (int i = threadIdx.y; i < 32; i += 8)
        out[(size_t)(c0 + i) * R + r0 + tx] = tile[tx][i];
}

// ---------------- transpose v slice of kv into g_vt ----------------
__global__ void vtrans_kernel()
{
    __shared__ float tile[32][33];
    const int t0  = blockIdx.x * 32;
    const int dv0 = blockIdx.y * 32;
    const int h   = blockIdx.z;
    const int tx  = threadIdx.x;
#pragma unroll
    for (int i = threadIdx.y; i < 32; i += 8)
        tile[i][tx] = g_kv[(size_t)(t0 + i) * (NH * (DN + DV)) + h * (DN + DV) + DN + dv0 + tx];
    __syncthreads();
#pragma unroll
    for (int i = threadIdx.y; i < 32; i += 8)
        g_vt[(size_t)h * DV * T_TOK + (size_t)(dv0 + i) * T_TOK + t0 + tx] = tile[tx][i];
}

// ---------------- tensor-core tf32 GEMM: BK=32, 3-stage cp.async, 2 CTAs/SM ----------------
// C[m,n] = alpha * sum_k A[m,k] * B[n,k]   (both operands K-major)
// DUALB: k-tiles with k0 >= KSPLIT(128) stream B rows from B2/ldb2.
// CLAMPK: K -> min(K, m0+128), with heavy-first m ordering (reversed blockIdx.y).
// NORMROW: epilogue multiplies row by 1/g_rowsum[z*T+row] and rounds (PV+attn_norm fusion).
#define NSTAGE 3
#define STG_WORDS 4096
#define GEMM_SMEM_BYTES (2 * NSTAGE * STG_WORDS * 4)
#define KSPLIT 128

template <bool SKIPN, bool CLAMPK, bool ROUNDC, bool DUALB, bool NORMROW>
__global__ __launch_bounds__(256, 2)
void tmma_gemm(const float* __restrict__ A, const float* __restrict__ B,
               float* __restrict__ C,
               int M, int N, int K, int lda, int ldb, int ldc,
               long long sA, long long sB, long long sC, float alpha,
               const float* __restrict__ B2, int ldb2)
{
    extern __shared__ float smf[];

    const int tid  = threadIdx.x;
    const int wid  = tid >> 5;
    const int lane = tid & 31;
    const int g    = lane >> 2;
    const int tig  = lane & 3;

    const int wm = (wid >> 1) * 32;
    const int wn = (wid & 1) * 64;

    const int z  = blockIdx.z;
    int m0 = blockIdx.y * 128;
    if (CLAMPK) m0 = (gridDim.y - 1 - blockIdx.y) * 128;   // heavy-first
    const int n0 = blockIdx.x * 128;

    if (SKIPN && n0 > m0 + 127) return;

    A += (size_t)z * sA;
    B += (size_t)z * sB;
    C += (size_t)z * sC;
    if (DUALB) B2 += (size_t)z * 0;   // B2 shared across heads (k_pe)

    int Keff = K;
    if (CLAMPK) Keff = min(K, m0 + 128);
    const int nkt = Keff >> 5;

    const uint32_t a_sm = (uint32_t)__cvta_generic_to_shared(smf);
    const uint32_t b_sm = a_sm + NSTAGE * STG_WORDS * 4;

    const int lrow = tid >> 3;          // 0..31
    const int lchk = tid & 7;           // chunk 0..7

    auto load_tile = [&](int kt) {
        const int st = kt % NSTAGE;
        const int k0 = kt << 5;
        const uint32_t asb = a_sm + (uint32_t)st * STG_WORDS * 4;
        const uint32_t bsb = b_sm + (uint32_t)st * STG_WORDS * 4;
#pragma unroll
        for (int i = 0; i < 4; i++) {
            const int row = i * 32 + lrow;
            const uint32_t dst = asb + (uint32_t)row * 128
                               + (uint32_t)((lchk ^ (row & 7)) << 4);
            const float* src = A + (size_t)(m0 + row) * lda + k0 + lchk * 4;
            CP_ASYNC16(dst, src, 16);
        }
        const float* Bp = B;
        int koff = k0, ldbp = ldb;
        if (DUALB && k0 >= KSPLIT) { Bp = B2; koff = k0 - KSPLIT; ldbp = ldb2; }
#pragma unroll
        for (int i = 0; i < 4; i++) {
            const int row = i * 32 + lrow;
            const bool in = (n0 + row < N);
            const uint32_t dst = bsb + (uint32_t)row * 128
                               + (uint32_t)((lchk ^ (row & 7)) << 4);
            const float* src = in ? (Bp + (size_t)(n0 + row) * ldbp + koff + lchk * 4) : Bp;
            CP_ASYNC16(dst, src, in ? 16 : 0);
        }
    };

    float acc[2][8][4];
#pragma unroll
    for (int mt = 0; mt < 2; mt++)
#pragma unroll
        for (int nt = 0; nt < 8; nt++)
#pragma unroll
            for (int r = 0; r < 4; r++) acc[mt][nt][r] = 0.0f;

    const int lr  = lane & 7;
    const int lhk = (lane >> 3) & 1;
    const int lhi = lane >> 4;

#pragma unroll
    for (int t = 0; t < NSTAGE - 1; t++) {
        if (t < nkt) load_tile(t);
        CP_COMMIT();
    }
    CP_WAIT1();
    __syncthreads();

    for (int kt = 0; kt < nkt; kt++) {
        if (kt + NSTAGE - 1 < nkt) load_tile(kt + NSTAGE - 1);
        CP_COMMIT();

        const int st = kt % NSTAGE;
        const uint32_t asb = a_sm + (uint32_t)st * STG_WORDS * 4;
        const uint32_t bsb = b_sm + (uint32_t)st * STG_WORDS * 4;

#pragma unroll
        for (int ks = 0; ks < 4; ks++) {
            uint32_t af[2][4];
#pragma unroll
            for (int mt = 0; mt < 2; mt++) {
                const int row = wm + mt * 16 + lhk * 8 + lr;
                const int chk = ks * 2 + lhi;
                const uint32_t addr = asb + (uint32_t)row * 128
                                    + (uint32_t)((chk ^ (row & 7)) << 4);
                ldsm_x4(af[mt][0], af[mt][1], af[mt][2], af[mt][3], addr);
            }
            uint32_t bf[8][2];
#pragma unroll
            for (int p = 0; p < 4; p++) {
                const int row = wn + p * 16 + lhi * 8 + lr;
                const int chk = ks * 2 + lhk;
                const uint32_t addr = bsb + (uint32_t)row * 128
                                    + (uint32_t)((chk ^ (row & 7)) << 4);
                ldsm_x4(bf[2 * p][0], bf[2 * p][1], bf[2 * p + 1][0], bf[2 * p + 1][1], addr);
            }
#pragma unroll
            for (int mt = 0; mt < 2; mt++)
#pragma unroll
                for (int nt = 0; nt < 8; nt++)
                    mma_tf32(acc[mt][nt], af[mt], bf[nt]);
        }

        CP_WAIT1();
        __syncthreads();
    }

    // ---- epilogue ----
#pragma unroll
    for (int mt = 0; mt < 2; mt++) {
        const int r0 = wm + mt * 16 + g;
        float inv0 = 1.0f, inv1 = 1.0f;
        if (NORMROW) {
            inv0 = 1.0f / g_rowsum[(size_t)z * T_TOK + m0 + r0];
            inv1 = 1.0f / g_rowsum[(size_t)z * T_TOK + m0 + r0 + 8];
        }
#pragma unroll
        for (int nt = 0; nt < 8; nt++) {
            const int col = n0 + wn + nt * 8 + 2 * tig;
            if (col < N) {
                float o0 = alpha * acc[mt][nt][0], o1 = alpha * acc[mt][nt][1];
                float o2 = alpha * acc[mt][nt][2], o3 = alpha * acc[mt][nt][3];
                if (NORMROW) {
                    o0 = round_tf32(o0 * inv0); o1 = round_tf32(o1 * inv0);
                    o2 = round_tf32(o2 * inv1); o3 = round_tf32(o3 * inv1);
                } else if (ROUNDC) {
                    o0 = round_tf32(o0); o1 = round_tf32(o1);
                    o2 = round_tf32(o2); o3 = round_tf32(o3);
                }
                *(float2*)&C[(size_t)(m0 + r0) * ldc + col]     = make_float2(o0, o1);
                *(float2*)&C[(size_t)(m0 + r0 + 8) * ldc + col] = make_float2(o2, o3);
            }
        }
    }
}

// ---------------- fused dual rmsnorm over g_qakva ----------------
__global__ void rmsnorm2_kernel(const float* __restrict__ gq, const float* __restrict__ gkv)
{
    const int row = blockIdx.x;
    const int sec = blockIdx.y;
    const int off = sec ? QL : 0;
    const int w   = sec ? KVL : QL;
    const float* gg = sec ? gkv : gq;
    float* p = g_qakva + (size_t)row * QKV_N + off;
    __shared__ float red[256];
    float s = 0.0f;
    for (int c = threadIdx.x; c < w; c += 256) { float v = p[c]; s += v * v; }
    red[threadIdx.x] = s;
    __syncthreads();
    for (int o = 128; o > 0; o >>= 1) {
        if (threadIdx.x < o) red[threadIdx.x] += red[threadIdx.x + o];
        __syncthreads();
    }
    const float r = rsqrtf(red[0] / (float)w + 1e-6f);
    for (int c = threadIdx.x; c < w; c += 256)
        p[c] = round_tf32(p[c] * r * gg[c]);
}

// ---------------- fused RoPE: y<NH -> q head y (+ round nope); y==NH -> k_pe ----------------
__global__ void rope_kernel(const int* __restrict__ positions)
{
    const int t = blockIdx.x;
    const int h = blockIdx.y;
    const int i = threadIdx.x;  // 0..31
    float* hp;
    float* p;
    if (h < NH) {
        hp = g_q + (size_t)t * (NH * DH) + h * DH;
        p  = hp + DN;
    } else {
        hp = nullptr;
        p  = g_qakva + (size_t)t * QKV_N + QL + KVL;
    }
    const float pos = (float)positions[t];
    const float inv = powf(10000.0f, -(float)(2 * i) / 64.0f);
    float sn, cs;
    sincosf(pos * inv, &sn, &cs);
    const float x1 = p[2 * i];
    const float x2 = p[2 * i + 1];
    p[2 * i]     = round_tf32(x1 * cs - x2 * sn);
    p[2 * i + 1] = round_tf32(x1 * sn + x2 * cs);
    if (h < NH) {
#pragma unroll
        for (int j = 0; j < 4; j++)
            hp[i * 4 + j] = round_tf32(hp[i * 4 + j]);
    }
}

// ---------------- single-pass causal softmax ----------------
__global__ __launch_bounds__(256)
void softmax_kernel(const int* __restrict__ positions)
{
    const int q = blockIdx.x;
    const int h = blockIdx.y;
    float* row = g_s + ((size_t)h * T_TOK + q) * T_TOK;
    const int pq = positions[q];
    const int jmax = ((q >> 7) + 1) << 7;       // 128..2048
    __shared__ float red[256];
    const int tid = threadIdx.x;

    float vals[8];
    int cnt = 0;
    float m = -INFINITY;
    for (int j = tid; j < jmax; j += 256) {
        float v = (positions[j] <= pq) ? row[j] : -INFINITY;
        vals[cnt++] = v;
        m = fmaxf(m, v);
    }
    red[tid] = m;
    __syncthreads();
    for (int o = 128; o > 0; o >>= 1) {
        if (tid < o) red[tid] = fmaxf(red[tid], red[tid + o]);
        __syncthreads();
    }
    m = red[0];
    __syncthreads();

    float s = 0.0f;
    cnt = 0;
    for (int j = tid; j < jmax; j += 256) {
        const float e = __expf(vals[cnt++] - m);
        s += e;
        row[j] = round_tf32(e);
    }
    red[tid] = s;
    __syncthreads();
    for (int o = 128; o > 0; o >>= 1) {
        if (tid < o) red[tid] += red[tid + o];
        __syncthreads();
    }
    if (tid == 0) g_rowsum[(size_t)h * T_TOK + q] = red[0];
}

// ---------------- launcher ----------------
extern "C" void kernel_launch(void* const* d_in, const int* in_sizes, int n_in,
                              void* d_out, int out_size)
{
    const int*   positions = (const int*)  d_in[0];
    const float* hidden    = (const float*)d_in[1];
    const float* wq_a      = (const float*)d_in[2];
    const float* gq        = (const float*)d_in[3];
    const float* wq_b      = (const float*)d_in[4];
    const float* wkv_a     = (const float*)d_in[5];
    const float* gkv       = (const float*)d_in[6];
    const float* wkv_b     = (const float*)d_in[7];
    const float* wo        = (const float*)d_in[8];
    float* out = (float*)d_out;

    float *qakva, *q, *kv, *s, *attn, *vt;
    float *hidr, *wqkva, *wqb, *wkvb, *wor;
    cudaGetSymbolAddress((void**)&qakva, g_qakva);
    cudaGetSymbolAddress((void**)&q,     g_q);
    cudaGetSymbolAddress((void**)&kv,    g_kv);
    cudaGetSymbolAddress((void**)&s,     g_s);
    cudaGetSymbolAddress((void**)&attn,  g_attn);
    cudaGetSymbolAddress((void**)&vt,    g_vt);
    cudaGetSymbolAddress((void**)&hidr,  g_hidr);
    cudaGetSymbolAddress((void**)&wqkva, g_wqkva);
    cudaGetSymbolAddress((void**)&wqb,   g_wqb);
    cudaGetSymbolAddress((void**)&wkvb,  g_wkvb);
    cudaGetSymbolAddress((void**)&wor,   g_wo);

    static cudaStream_t s1 = nullptr;
    static cudaEvent_t ev0 = nullptr, ev1 = nullptr;
    static bool attr_done = false;
    if (!attr_done) {
        cudaFuncSetAttribute(tmma_gemm<false,false,false,false,false>,
            cudaFuncAttributeMaxDynamicSharedMemorySize, GEMM_SMEM_BYTES);
        cudaFuncSetAttribute(tmma_gemm<false,false,true,false,false>,
            cudaFuncAttributeMaxDynamicSharedMemorySize, GEMM_SMEM_BYTES);
        cudaFuncSetAttribute(tmma_gemm<true,false,false,true,false>,
            cudaFuncAttributeMaxDynamicSharedMemorySize, GEMM_SMEM_BYTES);
        cudaFuncSetAttribute(tmma_gemm<false,true,false,false,true>,
            cudaFuncAttributeMaxDynamicSharedMemorySize, GEMM_SMEM_BYTES);
        cudaStreamCreateWithFlags(&s1, cudaStreamNonBlocking);
        cudaEventCreateWithFlags(&ev0, cudaEventDisableTiming);
        cudaEventCreateWithFlags(&ev1, cudaEventDisableTiming);
        attr_done = true;
    }

    const float scale = 1.0f / sqrtf((float)DH);
    const dim3 blk(256);
    const int  shm = GEMM_SMEM_BYTES;
    const dim3 tblk(32, 8);

    // 0. round hidden; round+transpose weights ([n][k]; wqa & wkva into one buffer)
    round_pass_kernel<<<1024, 256>>>(hidden, hidr, (int)((size_t)T_TOK * HID / 4));
    transpose_round_kernel<<<dim3(QL/32, HID/32), tblk>>>(wq_a, wqkva, HID, QL);
    transpose_round_kernel<<<dim3((KVL+DR)/32, HID/32), tblk>>>(
        wkv_a, wqkva + (size_t)QL * HID, HID, KVL+DR);
    transpose_round_kernel<<<dim3(NH*DH/32, QL/32), tblk>>>(wq_b, wqb, QL, NH*DH);
    transpose_round_kernel<<<dim3(NH*(DN+DV)/32, KVL/32), tblk>>>(wkv_b, wkvb, KVL, NH*(DN+DV));
    transpose_round_kernel<<<dim3(HID/32, NH*DV/32), tblk>>>(wo, wor, NH*DV, HID);

    // 1. [qa | kva] = hidr @ wqkva^T   [2048,2112] K=4096
    tmma_gemm<false,false,false,false,false><<<dim3((QKV_N+127)/128, T_TOK/128, 1), blk, shm>>>(
        hidr, wqkva, qakva, T_TOK, QKV_N, HID, HID, HID, QKV_N, 0, 0, 0, 1.0f,
        nullptr, 0);

    // 2. rmsnorm both sections -> rounded
    rmsnorm2_kernel<<<dim3(T_TOK, 2), 256>>>(gq, gkv);

    // fork: side stream runs GEMM4 + vtrans while main runs GEMM3 + rope
    cudaEventRecord(ev0, 0);
    cudaStreamWaitEvent(s1, ev0, 0);

    // 4. (s1) kv = ckv_ln @ wkvb^T    [2048,8192] K=512  (epilogue rounds)
    tmma_gemm<false,false,true,false,false><<<dim3(NH*(DN+DV)/128, T_TOK/128, 1), blk, shm, s1>>>(
        qakva + QL, wkvb, kv, T_TOK, NH*(DN+DV), KVL, QKV_N, KVL, NH*(DN+DV),
        0, 0, 0, 1.0f, nullptr, 0);
    // 6. (s1) v^T
    vtrans_kernel<<<dim3(T_TOK/32, DV/32, NH), tblk, 0, s1>>>();

    // 3. q = qa_ln @ wqb^T            [2048,6144] K=1536
    tmma_gemm<false,false,false,false,false><<<dim3(NH*DH/128, T_TOK/128, 1), blk, shm>>>(
        qakva, wqb, q, T_TOK, NH*DH, QL, QKV_N, QL, NH*DH, 0, 0, 0, 1.0f,
        nullptr, 0);

    // 5. rope q_pe (all heads, + round q_nope) and k_pe in one launch
    rope_kernel<<<dim3(T_TOK, NH + 1), 32>>>(positions);

    // join: scores needs kv (s1) and q/k_pe (main)
    cudaEventRecord(ev1, s1);
    cudaStreamWaitEvent(0, ev1, 0);

    // 7. scores[h] = scale * q[h] @ [k_nope | k_pe]^T  (dual-source B, causal tile skip)
    tmma_gemm<true,false,false,true,false><<<dim3(T_TOK/128, T_TOK/128, NH), blk, shm>>>(
        q, kv, s, T_TOK, T_TOK, DH, NH*DH, NH*(DN+DV), T_TOK,
        (long long)DH, (long long)(DN+DV), (long long)T_TOK*T_TOK, scale,
        qakva + QL + KVL, QKV_N);

    // 8. single-pass causal softmax (stores rounded exp, sums fp32)
    softmax_kernel<<<dim3(T_TOK, NH), 256>>>(positions);

    // 9. attn[h] = (exp_probs[h] @ vt[h]^T) / rowsum   (K clamp, heavy-first, norm fused)
    tmma_gemm<false,true,false,false,true><<<dim3(1, T_TOK/128, NH), blk, shm>>>(
        s, vt, attn, T_TOK, DV, T_TOK, T_TOK, T_TOK, NH*DV,
        (long long)T_TOK*T_TOK, (long long)DV*T_TOK, (long long)DV, 1.0f,
        nullptr, 0);

    // 10. out = attn @ wo^T           [2048,4096]
    tmma_gemm<false,false,false,false,false><<<dim3(HID/128, T_TOK/128, 1), blk, shm>>>(
        attn, wor, out, T_TOK, HID, NH*DV, NH*DV, NH*DV, HID, 0, 0, 0, 1.0f,
        nullptr, 0);
}

// round 14
// speedup vs baseline: 1.2455x; 1.0085x over previous
#include <cuda_runtime.h>
#include <cuda_bf16.h>
#include <math.h>
#include <stdint.h>

// ---------------- problem constants ----------------
#define T_TOK  2048
#define HID    4096
#define NH     32
#define DN     128   // qk_nope
#define DR     64    // qk_rope
#define DH     192   // qk_head
#define DV     128   // v_head
#define QL     1536  // q_lora
#define KVL    512   // kv_lora
#define QKV_N  (QL + KVL + DR)   // 2112 combined first-projection width

// ---------------- device scratch ----------------
__device__ float g_qakva [(size_t)T_TOK * QKV_N];       // [t][ qa(1536) | c_kv(512) | k_pe(64) ]
__device__ float g_q     [(size_t)T_TOK * NH * DH];
__device__ float g_kv    [(size_t)T_TOK * NH * (DN + DV)];
__device__ float g_s     [(size_t)NH * T_TOK * T_TOK];
__device__ float g_attn  [(size_t)T_TOK * NH * DV];
__device__ float g_rowsum[(size_t)NH * T_TOK];
__device__ float g_vt    [(size_t)NH * DV * T_TOK];     // v transposed per head [h][dv][t]
// tf32-rounded (and transposed, for weights) copies of raw inputs
__device__ float g_hidr  [(size_t)T_TOK * HID];
__device__ float g_wqkva [(size_t)QKV_N * HID];         // [n][k]  rows: wqa | wkva
__device__ float g_wqb   [(size_t)NH * DH * QL];        // [n][k]
__device__ float g_wkvb  [(size_t)NH * (DN + DV) * KVL];// [n][k]
__device__ float g_wo    [(size_t)HID * NH * DV];       // [n][k]

// ---------------- helpers ----------------
__device__ __forceinline__ float round_tf32(float x) {
    float y;
    asm("cvt.rna.tf32.f32 %0, %1;" : "=f"(y) : "f"(x));
    return y;
}

__device__ __forceinline__ void mma_tf32(float* c, const uint32_t* a, const uint32_t* b) {
    asm volatile(
        "mma.sync.aligned.m16n8k8.row.col.f32.tf32.tf32.f32 "
        "{%0,%1,%2,%3}, {%4,%5,%6,%7}, {%8,%9}, {%0,%1,%2,%3};"
        : "+f"(c[0]), "+f"(c[1]), "+f"(c[2]), "+f"(c[3])
        : "r"(a[0]), "r"(a[1]), "r"(a[2]), "r"(a[3]), "r"(b[0]), "r"(b[1]));
}

__device__ __forceinline__ void ldsm_x4(uint32_t& r0, uint32_t& r1, uint32_t& r2,
                                        uint32_t& r3, uint32_t addr) {
    asm volatile("ldmatrix.sync.aligned.m8n8.x4.shared.b16 {%0,%1,%2,%3}, [%4];"
                 : "=r"(r0), "=r"(r1), "=r"(r2), "=r"(r3) : "r"(addr));
}

#define CP_ASYNC16(dst_u32, src_ptr, sz) \
    asm volatile("cp.async.cg.shared.global [%0], [%1], 16, %2;" \
        :: "r"(dst_u32), "l"(src_ptr), "r"(sz))
#define CP_COMMIT() asm volatile("cp.async.commit_group;" ::: "memory")
#define CP_WAIT1()  asm volatile("cp.async.wait_group 1;" ::: "memory")
#define CP_WAIT0()  asm volatile("cp.async.wait_group 0;" ::: "memory")

// ---------------- elementwise tf32 rounding pass ----------------
__global__ void round_pass_kernel(const float* __restrict__ in, float* __restrict__ out,
                                  int n4)
{
    const int stride = gridDim.x * blockDim.x;
    for (int i = blockIdx.x * blockDim.x + threadIdx.x; i < n4; i += stride) {
        float4 v = ((const float4*)in)[i];
        v.x = round_tf32(v.x); v.y = round_tf32(v.y);
        v.z = round_tf32(v.z); v.w = round_tf32(v.w);
        ((float4*)out)[i] = v;
    }
}

// ---------------- fused round + transpose: in[R][C] -> out[C][R] ----------------
__global__ void transpose_round_kernel(const float* __restrict__ in,
                                       float* __restrict__ out, int R, int C)
{
    __shared__ float tile[32][33];
    const int c0 = blockIdx.x * 32;
    const int r0 = blockIdx.y * 32;
    const int tx = threadIdx.x;
#pragma unroll
    for (int i = threadIdx.y; i < 32; i += 8)
        tile[i][tx] = round_tf32(in[(size_t)(r0 + i) * C + c0 + tx]);
    __syncthreads();
#pragma unroll
    for (int i = threadIdx.y; i < 32; i += 8)
        out[(size_t)(c0 + i) * R + r0 + tx] = tile[tx][i];
}

// ---------------- transpose v slice of kv into g_vt ----------------
__global__ void vtrans_kernel()
{
    __shared__ float tile[32][33];
    const int t0  = blockIdx.x * 32;
    const int dv0 = blockIdx.y * 32;
    const int h   = blockIdx.z;
    const int tx  = threadIdx.x;
#pragma unroll
    for (int i = threadIdx.y; i < 32; i += 8)
        tile[i][tx] = g_kv[(size_t)(t0 + i) * (NH * (DN + DV)) + h * (DN + DV) + DN + dv0 + tx];
    __syncthreads();
#pragma unroll
    for (int i = threadIdx.y; i < 32; i += 8)
        g_vt[(size_t)h * DV * T_TOK + (size_t)(dv0 + i) * T_TOK + t0 + tx] = tile[tx][i];
}

// ---------------- tensor-core tf32 GEMM: BK=32, 3-stage cp.async, 2 CTAs/SM ----------------
// C[m,n] = alpha * sum_k A[m,k] * B[n,k]   (both operands K-major)
// DUALB: k-tiles with k0 >= KSPLIT(128) stream B rows from B2/ldb2.
// CLAMPK: K -> min(K, m0+128), heavy-first m ordering.
// NORMROW: epilogue multiplies row by 1/g_rowsum[(z+zoff)*T+row] and rounds.
#define NSTAGE 3
#define STG_WORDS 4096
#define GEMM_SMEM_BYTES (2 * NSTAGE * STG_WORDS * 4)
#define KSPLIT 128

template <bool SKIPN, bool CLAMPK, bool ROUNDC, bool DUALB, bool NORMROW>
__global__ __launch_bounds__(256, 2)
void tmma_gemm(const float* __restrict__ A, const float* __restrict__ B,
               float* __restrict__ C,
               int M, int N, int K, int lda, int ldb, int ldc,
               long long sA, long long sB, long long sC, float alpha,
               const float* __restrict__ B2, int ldb2, int zoff)
{
    extern __shared__ float smf[];

    const int tid  = threadIdx.x;
    const int wid  = tid >> 5;
    const int lane = tid & 31;
    const int g    = lane >> 2;
    const int tig  = lane & 3;

    const int wm = (wid >> 1) * 32;
    const int wn = (wid & 1) * 64;

    const int z  = blockIdx.z;
    int m0 = blockIdx.y * 128;
    if (CLAMPK) m0 = (gridDim.y - 1 - blockIdx.y) * 128;   // heavy-first
    const int n0 = blockIdx.x * 128;

    if (SKIPN && n0 > m0 + 127) return;

    A += (size_t)z * sA;
    B += (size_t)z * sB;
    C += (size_t)z * sC;

    int Keff = K;
    if (CLAMPK) Keff = min(K, m0 + 128);
    const int nkt = Keff >> 5;

    const uint32_t a_sm = (uint32_t)__cvta_generic_to_shared(smf);
    const uint32_t b_sm = a_sm + NSTAGE * STG_WORDS * 4;

    const int lrow = tid >> 3;          // 0..31
    const int lchk = tid & 7;           // chunk 0..7

    auto load_tile = [&](int kt) {
        const int st = kt % NSTAGE;
        const int k0 = kt << 5;
        const uint32_t asb = a_sm + (uint32_t)st * STG_WORDS * 4;
        const uint32_t bsb = b_sm + (uint32_t)st * STG_WORDS * 4;
#pragma unroll
        for (int i = 0; i < 4; i++) {
            const int row = i * 32 + lrow;
            const uint32_t dst = asb + (uint32_t)row * 128
                               + (uint32_t)((lchk ^ (row & 7)) << 4);
            const float* src = A + (size_t)(m0 + row) * lda + k0 + lchk * 4;
            CP_ASYNC16(dst, src, 16);
        }
        const float* Bp = B;
        int koff = k0, ldbp = ldb;
        if (DUALB && k0 >= KSPLIT) { Bp = B2; koff = k0 - KSPLIT; ldbp = ldb2; }
#pragma unroll
        for (int i = 0; i < 4; i++) {
            const int row = i * 32 + lrow;
            const bool in = (n0 + row < N);
            const uint32_t dst = bsb + (uint32_t)row * 128
                               + (uint32_t)((lchk ^ (row & 7)) << 4);
            const float* src = in ? (Bp + (size_t)(n0 + row) * ldbp + koff + lchk * 4) : Bp;
            CP_ASYNC16(dst, src, in ? 16 : 0);
        }
    };

    float acc[2][8][4];
#pragma unroll
    for (int mt = 0; mt < 2; mt++)
#pragma unroll
        for (int nt = 0; nt < 8; nt++)
#pragma unroll
            for (int r = 0; r < 4; r++) acc[mt][nt][r] = 0.0f;

    const int lr  = lane & 7;
    const int lhk = (lane >> 3) & 1;
    const int lhi = lane >> 4;

#pragma unroll
    for (int t = 0; t < NSTAGE - 1; t++) {
        if (t < nkt) load_tile(t);
        CP_COMMIT();
    }
    CP_WAIT1();
    __syncthreads();

    for (int kt = 0; kt < nkt; kt++) {
        if (kt + NSTAGE - 1 < nkt) load_tile(kt + NSTAGE - 1);
        CP_COMMIT();

        const int st = kt % NSTAGE;
        const uint32_t asb = a_sm + (uint32_t)st * STG_WORDS * 4;
        const uint32_t bsb = b_sm + (uint32_t)st * STG_WORDS * 4;

#pragma unroll
        for (int ks = 0; ks < 4; ks++) {
            uint32_t af[2][4];
#pragma unroll
            for (int mt = 0; mt < 2; mt++) {
                const int row = wm + mt * 16 + lhk * 8 + lr;
                const int chk = ks * 2 + lhi;
                const uint32_t addr = asb + (uint32_t)row * 128
                                    + (uint32_t)((chk ^ (row & 7)) << 4);
                ldsm_x4(af[mt][0], af[mt][1], af[mt][2], af[mt][3], addr);
            }
            uint32_t bf[8][2];
#pragma unroll
            for (int p = 0; p < 4; p++) {
                const int row = wn + p * 16 + lhi * 8 + lr;
                const int chk = ks * 2 + lhk;
                const uint32_t addr = bsb + (uint32_t)row * 128
                                    + (uint32_t)((chk ^ (row & 7)) << 4);
                ldsm_x4(bf[2 * p][0], bf[2 * p][1], bf[2 * p + 1][0], bf[2 * p + 1][1], addr);
            }
#pragma unroll
            for (int mt = 0; mt < 2; mt++)
#pragma unroll
                for (int nt = 0; nt < 8; nt++)
                    mma_tf32(acc[mt][nt], af[mt], bf[nt]);
        }

        CP_WAIT1();
        __syncthreads();
    }

    // ---- epilogue ----
#pragma unroll
    for (int mt = 0; mt < 2; mt++) {
        const int r0 = wm + mt * 16 + g;
        float inv0 = 1.0f, inv1 = 1.0f;
        if (NORMROW) {
            inv0 = 1.0f / g_rowsum[(size_t)(z + zoff) * T_TOK + m0 + r0];
            inv1 = 1.0f / g_rowsum[(size_t)(z + zoff) * T_TOK + m0 + r0 + 8];
        }
#pragma unroll
        for (int nt = 0; nt < 8; nt++) {
            const int col = n0 + wn + nt * 8 + 2 * tig;
            if (col < N) {
                float o0 = alpha * acc[mt][nt][0], o1 = alpha * acc[mt][nt][1];
                float o2 = alpha * acc[mt][nt][2], o3 = alpha * acc[mt][nt][3];
                if (NORMROW) {
                    o0 = round_tf32(o0 * inv0); o1 = round_tf32(o1 * inv0);
                    o2 = round_tf32(o2 * inv1); o3 = round_tf32(o3 * inv1);
                } else if (ROUNDC) {
                    o0 = round_tf32(o0); o1 = round_tf32(o1);
                    o2 = round_tf32(o2); o3 = round_tf32(o3);
                }
                *(float2*)&C[(size_t)(m0 + r0) * ldc + col]     = make_float2(o0, o1);
                *(float2*)&C[(size_t)(m0 + r0 + 8) * ldc + col] = make_float2(o2, o3);
            }
        }
    }
}

// ---------------- fused dual rmsnorm over g_qakva ----------------
__global__ void rmsnorm2_kernel(const float* __restrict__ gq, const float* __restrict__ gkv)
{
    const int row = blockIdx.x;
    const int sec = blockIdx.y;
    const int off = sec ? QL : 0;
    const int w   = sec ? KVL : QL;
    const float* gg = sec ? gkv : gq;
    float* p = g_qakva + (size_t)row * QKV_N + off;
    __shared__ float red[256];
    float s = 0.0f;
    for (int c = threadIdx.x; c < w; c += 256) { float v = p[c]; s += v * v; }
    red[threadIdx.x] = s;
    __syncthreads();
    for (int o = 128; o > 0; o >>= 1) {
        if (threadIdx.x < o) red[threadIdx.x] += red[threadIdx.x + o];
        __syncthreads();
    }
    const float r = rsqrtf(red[0] / (float)w + 1e-6f);
    for (int c = threadIdx.x; c < w; c += 256)
        p[c] = round_tf32(p[c] * r * gg[c]);
}

// ---------------- fused RoPE: y<NH -> q head y (+ round nope); y==NH -> k_pe ----------------
__global__ void rope_kernel(const int* __restrict__ positions)
{
    const int t = blockIdx.x;
    const int h = blockIdx.y;
    const int i = threadIdx.x;  // 0..31
    float* hp;
    float* p;
    if (h < NH) {
        hp = g_q + (size_t)t * (NH * DH) + h * DH;
        p  = hp + DN;
    } else {
        hp = nullptr;
        p  = g_qakva + (size_t)t * QKV_N + QL + KVL;
    }
    const float pos = (float)positions[t];
    const float inv = powf(10000.0f, -(float)(2 * i) / 64.0f);
    float sn, cs;
    sincosf(pos * inv, &sn, &cs);
    const float x1 = p[2 * i];
    const float x2 = p[2 * i + 1];
    p[2 * i]     = round_tf32(x1 * cs - x2 * sn);
    p[2 * i + 1] = round_tf32(x1 * sn + x2 * cs);
    if (h < NH) {
#pragma unroll
        for (int j = 0; j < 4; j++)
            hp[i * 4 + j] = round_tf32(hp[i * 4 + j]);
    }
}

// ---------------- single-pass causal softmax (head range offset h0) ----------------
__global__ __launch_bounds__(256)
void softmax_kernel(const int* __restrict__ positions, int h0)
{
    const int q = blockIdx.x;
    const int h = blockIdx.y + h0;
    float* row = g_s + ((size_t)h * T_TOK + q) * T_TOK;
    const int pq = positions[q];
    const int jmax = ((q >> 7) + 1) << 7;       // 128..2048
    __shared__ float red[256];
    const int tid = threadIdx.x;

    float vals[8];
    int cnt = 0;
    float m = -INFINITY;
    for (int j = tid; j < jmax; j += 256) {
        float v = (positions[j] <= pq) ? row[j] : -INFINITY;
        vals[cnt++] = v;
        m = fmaxf(m, v);
    }
    red[tid] = m;
    __syncthreads();
    for (int o = 128; o > 0; o >>= 1) {
        if (tid < o) red[tid] = fmaxf(red[tid], red[tid + o]);
        __syncthreads();
    }
    m = red[0];
    __syncthreads();

    float s = 0.0f;
    cnt = 0;
    for (int j = tid; j < jmax; j += 256) {
        const float e = __expf(vals[cnt++] - m);
        s += e;
        row[j] = round_tf32(e);
    }
    red[tid] = s;
    __syncthreads();
    for (int o = 128; o > 0; o >>= 1) {
        if (tid < o) red[tid] += red[tid + o];
        __syncthreads();
    }
    if (tid == 0) g_rowsum[(size_t)h * T_TOK + q] = red[0];
}

// ---------------- launcher ----------------
extern "C" void kernel_launch(void* const* d_in, const int* in_sizes, int n_in,
                              void* d_out, int out_size)
{
    const int*   positions = (const int*)  d_in[0];
    const float* hidden    = (const float*)d_in[1];
    const float* wq_a      = (const float*)d_in[2];
    const float* gq        = (const float*)d_in[3];
    const float* wq_b      = (const float*)d_in[4];
    const float* wkv_a     = (const float*)d_in[5];
    const float* gkv       = (const float*)d_in[6];
    const float* wkv_b     = (const float*)d_in[7];
    const float* wo        = (const float*)d_in[8];
    float* out = (float*)d_out;

    float *qakva, *q, *kv, *s, *attn, *vt;
    float *hidr, *wqkva, *wqb, *wkvb, *wor;
    cudaGetSymbolAddress((void**)&qakva, g_qakva);
    cudaGetSymbolAddress((void**)&q,     g_q);
    cudaGetSymbolAddress((void**)&kv,    g_kv);
    cudaGetSymbolAddress((void**)&s,     g_s);
    cudaGetSymbolAddress((void**)&attn,  g_attn);
    cudaGetSymbolAddress((void**)&vt,    g_vt);
    cudaGetSymbolAddress((void**)&hidr,  g_hidr);
    cudaGetSymbolAddress((void**)&wqkva, g_wqkva);
    cudaGetSymbolAddress((void**)&wqb,   g_wqb);
    cudaGetSymbolAddress((void**)&wkvb,  g_wkvb);
    cudaGetSymbolAddress((void**)&wor,   g_wo);

    static cudaStream_t s1 = nullptr, s2 = nullptr;
    static cudaEvent_t evRoot = nullptr, evP1 = nullptr, evP2 = nullptr, evF = nullptr;
    static cudaEvent_t evM = nullptr, evS1 = nullptr, evJ = nullptr;
    static bool attr_done = false;
    if (!attr_done) {
        cudaFuncSetAttribute(tmma_gemm<false,false,false,false,false>,
            cudaFuncAttributeMaxDynamicSharedMemorySize, GEMM_SMEM_BYTES);
        cudaFuncSetAttribute(tmma_gemm<false,false,true,false,false>,
            cudaFuncAttributeMaxDynamicSharedMemorySize, GEMM_SMEM_BYTES);
        cudaFuncSetAttribute(tmma_gemm<true,false,false,true,false>,
            cudaFuncAttributeMaxDynamicSharedMemorySize, GEMM_SMEM_BYTES);
        cudaFuncSetAttribute(tmma_gemm<false,true,false,false,true>,
            cudaFuncAttributeMaxDynamicSharedMemorySize, GEMM_SMEM_BYTES);
        cudaStreamCreateWithFlags(&s1, cudaStreamNonBlocking);
        cudaStreamCreateWithFlags(&s2, cudaStreamNonBlocking);
        cudaEventCreateWithFlags(&evRoot, cudaEventDisableTiming);
        cudaEventCreateWithFlags(&evP1, cudaEventDisableTiming);
        cudaEventCreateWithFlags(&evP2, cudaEventDisableTiming);
        cudaEventCreateWithFlags(&evF,  cudaEventDisableTiming);
        cudaEventCreateWithFlags(&evM,  cudaEventDisableTiming);
        cudaEventCreateWithFlags(&evS1, cudaEventDisableTiming);
        cudaEventCreateWithFlags(&evJ,  cudaEventDisableTiming);
        attr_done = true;
    }

    const float scale = 1.0f / sqrtf((float)DH);
    const dim3 blk(256);
    const int  shm = GEMM_SMEM_BYTES;
    const dim3 tblk(32, 8);
    const int  NHH = NH / 2;   // heads per attention stream

    // ---- root fork: s1/s2 must be event-rooted in the capture graph ----
    cudaEventRecord(evRoot, 0);
    cudaStreamWaitEvent(s1, evRoot, 0);
    cudaStreamWaitEvent(s2, evRoot, 0);

    // ---- preprocessing fork ----
    // main: hidr round;  s1: wqa+wkva transposes (needed by GEMM1);
    // s2: wqb+wkvb+wo transposes (overlap with GEMM1; needed by GEMM3/4/wo).
    round_pass_kernel<<<1024, 256>>>(hidden, hidr, (int)((size_t)T_TOK * HID / 4));
    transpose_round_kernel<<<dim3(QL/32, HID/32), tblk, 0, s1>>>(wq_a, wqkva, HID, QL);
    transpose_round_kernel<<<dim3((KVL+DR)/32, HID/32), tblk, 0, s1>>>(
        wkv_a, wqkva + (size_t)QL * HID, HID, KVL+DR);
    transpose_round_kernel<<<dim3(NH*DH/32, QL/32), tblk, 0, s2>>>(wq_b, wqb, QL, NH*DH);
    transpose_round_kernel<<<dim3(NH*(DN+DV)/32, KVL/32), tblk, 0, s2>>>(
        wkv_b, wkvb, KVL, NH*(DN+DV));
    transpose_round_kernel<<<dim3(HID/32, NH*DV/32), tblk, 0, s2>>>(wo, wor, NH*DV, HID);
    cudaEventRecord(evP1, s1);
    cudaEventRecord(evP2, s2);
    cudaStreamWaitEvent(0, evP1, 0);

    // 1. [qa | kva] = hidr @ wqkva^T   [2048,2112] K=4096
    tmma_gemm<false,false,false,false,false><<<dim3((QKV_N+127)/128, T_TOK/128, 1), blk, shm>>>(
        hidr, wqkva, qakva, T_TOK, QKV_N, HID, HID, HID, QKV_N, 0, 0, 0, 1.0f,
        nullptr, 0, 0);

    // 2. rmsnorm both sections -> rounded
    rmsnorm2_kernel<<<dim3(T_TOK, 2), 256>>>(gq, gkv);

    // fork: s1 runs GEMM4 + vtrans while main runs GEMM3 + rope
    cudaEventRecord(evF, 0);
    cudaStreamWaitEvent(s1, evF, 0);
    cudaStreamWaitEvent(s1, evP2, 0);   // wkvb ready
    cudaStreamWaitEvent(0,  evP2, 0);   // wqb/wo ready

    // 4. (s1) kv = ckv_ln @ wkvb^T    [2048,8192] K=512  (epilogue rounds)
    tmma_gemm<false,false,true,false,false><<<dim3(NH*(DN+DV)/128, T_TOK/128, 1), blk, shm, s1>>>(
        qakva + QL, wkvb, kv, T_TOK, NH*(DN+DV), KVL, QKV_N, KVL, NH*(DN+DV),
        0, 0, 0, 1.0f, nullptr, 0, 0);
    // (s1) v^T
    vtrans_kernel<<<dim3(T_TOK/32, DV/32, NH), tblk, 0, s1>>>();

    // 3. q = qa_ln @ wqb^T            [2048,6144] K=1536
    tmma_gemm<false,false,false,false,false><<<dim3(NH*DH/128, T_TOK/128, 1), blk, shm>>>(
        qakva, wqb, q, T_TOK, NH*DH, QL, QKV_N, QL, NH*DH, 0, 0, 0, 1.0f,
        nullptr, 0, 0);

    // 5. rope q_pe (all heads, + round q_nope) and k_pe in one launch
    rope_kernel<<<dim3(T_TOK, NH + 1), 32>>>(positions);

    // cross-sync: both attention streams need q+rope (main) and kv+vt (s1)
    cudaEventRecord(evM, 0);
    cudaEventRecord(evS1, s1);
    cudaStreamWaitEvent(0,  evS1, 0);
    cudaStreamWaitEvent(s1, evM, 0);

    // ---- attention split: heads [0,16) on main, [16,32) on s1 ----
    for (int c = 0; c < 2; c++) {
        cudaStream_t st = c ? s1 : (cudaStream_t)0;
        const int h0 = c * NHH;
        // scores = scale * q @ [k_nope | k_pe]^T   (dual-source B, causal skip)
        tmma_gemm<true,false,false,true,false><<<dim3(T_TOK/128, T_TOK/128, NHH), blk, shm, st>>>(
            q + h0 * DH, kv + h0 * (DN + DV), s + (size_t)h0 * T_TOK * T_TOK,
            T_TOK, T_TOK, DH, NH*DH, NH*(DN+DV), T_TOK,
            (long long)DH, (long long)(DN+DV), (long long)T_TOK*T_TOK, scale,
            qakva + QL + KVL, QKV_N, 0);
        // softmax
        softmax_kernel<<<dim3(T_TOK, NHH), 256, 0, st>>>(positions, h0);
        // PV + row-normalize (K clamp, heavy-first)
        tmma_gemm<false,true,false,false,true><<<dim3(1, T_TOK/128, NHH), blk, shm, st>>>(
            s + (size_t)h0 * T_TOK * T_TOK, vt + (size_t)h0 * DV * T_TOK, attn + h0 * DV,
            T_TOK, DV, T_TOK, T_TOK, T_TOK, NH*DV,
            (long long)T_TOK*T_TOK, (long long)DV*T_TOK, (long long)DV, 1.0f,
            nullptr, 0, h0);
    }

    // join attention streams
    cudaEventRecord(evJ, s1);
    cudaStreamWaitEvent(0, evJ, 0);

    // 10. out = attn @ wo^T           [2048,4096]
    tmma_gemm<false,false,false,false,false><<<dim3(HID/128, T_TOK/128, 1), blk, shm>>>(
        attn, wor, out, T_TOK, HID, NH*DV, NH*DV, NH*DV, HID, 0, 0, 0, 1.0f,
        nullptr, 0, 0);
}

// round 15
// speedup vs baseline: 1.3426x; 1.0780x over previous
#include <cuda_runtime.h>
#include <cuda_bf16.h>
#include <math.h>
#include <stdint.h>

// ---------------- problem constants ----------------
#define T_TOK  2048
#define HID    4096
#define NH     32
#define DN     128   // qk_nope
#define DR     64    // qk_rope
#define DH     192   // qk_head
#define DV     128   // v_head
#define QL     1536  // q_lora
#define KVL    512   // kv_lora
#define QKV_N  (QL + KVL + DR)   // 2112 combined first-projection width

// ---------------- device scratch ----------------
__device__ float g_qakva [(size_t)T_TOK * QKV_N];
__device__ float g_q     [(size_t)T_TOK * NH * DH];
__device__ float g_kv    [(size_t)T_TOK * NH * (DN + DV)];
__device__ float g_s     [(size_t)NH * T_TOK * T_TOK];
__device__ float g_attn  [(size_t)T_TOK * NH * DV];
__device__ float g_rowsum[(size_t)NH * T_TOK];
__device__ float g_vt    [(size_t)NH * DV * T_TOK];
__device__ float g_hidr  [(size_t)T_TOK * HID];
__device__ float g_wqkva [(size_t)QKV_N * HID];
__device__ float g_wqb   [(size_t)NH * DH * QL];
__device__ float g_wkvb  [(size_t)NH * (DN + DV) * KVL];
__device__ float g_wo    [(size_t)HID * NH * DV];

// ---------------- helpers ----------------
__device__ __forceinline__ float round_tf32(float x) {
    float y;
    asm("cvt.rna.tf32.f32 %0, %1;" : "=f"(y) : "f"(x));
    return y;
}

__device__ __forceinline__ void mma_tf32(float* c, const uint32_t* a, const uint32_t* b) {
    asm volatile(
        "mma.sync.aligned.m16n8k8.row.col.f32.tf32.tf32.f32 "
        "{%0,%1,%2,%3}, {%4,%5,%6,%7}, {%8,%9}, {%0,%1,%2,%3};"
        : "+f"(c[0]), "+f"(c[1]), "+f"(c[2]), "+f"(c[3])
        : "r"(a[0]), "r"(a[1]), "r"(a[2]), "r"(a[3]), "r"(b[0]), "r"(b[1]));
}

__device__ __forceinline__ void ldsm_x4(uint32_t& r0, uint32_t& r1, uint32_t& r2,
                                        uint32_t& r3, uint32_t addr) {
    asm volatile("ldmatrix.sync.aligned.m8n8.x4.shared.b16 {%0,%1,%2,%3}, [%4];"
                 : "=r"(r0), "=r"(r1), "=r"(r2), "=r"(r3) : "r"(addr));
}

#define CP_ASYNC16(dst_u32, src_ptr, sz) \
    asm volatile("cp.async.cg.shared.global [%0], [%1], 16, %2;" \
        :: "r"(dst_u32), "l"(src_ptr), "r"(sz))
#define CP_COMMIT() asm volatile("cp.async.commit_group;" ::: "memory")
#define CP_WAIT1()  asm volatile("cp.async.wait_group 1;" ::: "memory")

// ---------------- elementwise tf32 rounding pass ----------------
__global__ void round_pass_kernel(const float* __restrict__ in, float* __restrict__ out,
                                  int n4)
{
    const int stride = gridDim.x * blockDim.x;
    for (int i = blockIdx.x * blockDim.x + threadIdx.x; i < n4; i += stride) {
        float4 v = ((const float4*)in)[i];
        v.x = round_tf32(v.x); v.y = round_tf32(v.y);
        v.z = round_tf32(v.z); v.w = round_tf32(v.w);
        ((float4*)out)[i] = v;
    }
}

// ---------------- fused round + transpose: in[R][C] -> out[C][R] ----------------
__global__ void transpose_round_kernel(const float* __restrict__ in,
                                       float* __restrict__ out, int R, int C)
{
    __shared__ float tile[32][33];
    const int c0 = blockIdx.x * 32;
    const int r0 = blockIdx.y * 32;
    const int tx = threadIdx.x;
#pragma unroll
    for (int i = threadIdx.y; i < 32; i += 8)
        tile[i][tx] = round_tf32(in[(size_t)(r0 + i) * C + c0 + tx]);
    __syncthreads();
#pragma unroll
    for (int i = threadIdx.y; i < 32; i += 8)
        out[(size_t)(c0 + i) * R + r0 + tx] = tile[tx][i];
}

// ---------------- transpose v slice of kv into g_vt ----------------
__global__ void vtrans_kernel()
{
    __shared__ float tile[32][33];
    const int t0  = blockIdx.x * 32;
    const int dv0 = blockIdx.y * 32;
    const int h   = blockIdx.z;
    const int tx  = threadIdx.x;
#pragma unroll
    for (int i = threadIdx.y; i < 32; i += 8)
        tile[i][tx] = g_kv[(size_t)(t0 + i) * (NH * (DN + DV)) + h * (DN + DV) + DN + dv0 + tx];
    __syncthreads();
#pragma unroll
    for (int i = threadIdx.y; i < 32; i += 8)
        g_vt[(size_t)h * DV * T_TOK + (size_t)(dv0 + i) * T_TOK + t0 + tx] = tile[tx][i];
}

// ---------------- tensor-core tf32 GEMM: BK=32, 3-stage cp.async, 2 CTAs/SM ----------------
// C[m,n] = alpha * sum_k A[m,k] * B[n,k]
// EPI: 0=raw store, 1=round, 2=rowsum-normalize+round, 3=rope k_pe cols (GEMM1),
//      4=rope pe / round nope per head (GEMM3)
// DUALB: k0>=KSPLIT reads B2. CLAMPK: K->min(K,m0+128), heavy-first within grid.
// moff: m-tile offset (128-row units).
#define NSTAGE 3
#define STG_WORDS 4096
#define GEMM_SMEM_BYTES (2 * NSTAGE * STG_WORDS * 4)
#define KSPLIT 128

template <bool SKIPN, bool CLAMPK, int EPI, bool DUALB>
__global__ __launch_bounds__(256, 2)
void tmma_gemm(const float* __restrict__ A, const float* __restrict__ B,
               float* __restrict__ C,
               int M, int N, int K, int lda, int ldb, int ldc,
               long long sA, long long sB, long long sC, float alpha,
               const float* __restrict__ B2, int ldb2, int zoff, int moff,
               const int* __restrict__ positions)
{
    extern __shared__ float smf[];

    const int tid  = threadIdx.x;
    const int wid  = tid >> 5;
    const int lane = tid & 31;
    const int g    = lane >> 2;
    const int tig  = lane & 3;

    const int wm = (wid >> 1) * 32;
    const int wn = (wid & 1) * 64;

    const int z  = blockIdx.z;
    int m0;
    if (CLAMPK) m0 = (moff + gridDim.y - 1 - blockIdx.y) * 128;   // heavy-first
    else        m0 = (moff + blockIdx.y) * 128;
    const int n0 = blockIdx.x * 128;

    if (SKIPN && n0 > m0 + 127) return;

    A += (size_t)z * sA;
    B += (size_t)z * sB;
    C += (size_t)z * sC;

    int Keff = K;
    if (CLAMPK) Keff = min(K, m0 + 128);
    const int nkt = Keff >> 5;

    const uint32_t a_sm = (uint32_t)__cvta_generic_to_shared(smf);
    const uint32_t b_sm = a_sm + NSTAGE * STG_WORDS * 4;

    const int lrow = tid >> 3;
    const int lchk = tid & 7;

    auto load_tile = [&](int kt) {
        const int st = kt % NSTAGE;
        const int k0 = kt << 5;
        const uint32_t asb = a_sm + (uint32_t)st * STG_WORDS * 4;
        const uint32_t bsb = b_sm + (uint32_t)st * STG_WORDS * 4;
#pragma unroll
        for (int i = 0; i < 4; i++) {
            const int row = i * 32 + lrow;
            const uint32_t dst = asb + (uint32_t)row * 128
                               + (uint32_t)((lchk ^ (row & 7)) << 4);
            const float* src = A + (size_t)(m0 + row) * lda + k0 + lchk * 4;
            CP_ASYNC16(dst, src, 16);
        }
        const float* Bp = B;
        int koff = k0, ldbp = ldb;
        if (DUALB && k0 >= KSPLIT) { Bp = B2; koff = k0 - KSPLIT; ldbp = ldb2; }
#pragma unroll
        for (int i = 0; i < 4; i++) {
            const int row = i * 32 + lrow;
            const bool in = (n0 + row < N);
            const uint32_t dst = bsb + (uint32_t)row * 128
                               + (uint32_t)((lchk ^ (row & 7)) << 4);
            const float* src = in ? (Bp + (size_t)(n0 + row) * ldbp + koff + lchk * 4) : Bp;
            CP_ASYNC16(dst, src, in ? 16 : 0);
        }
    };

    float acc[2][8][4];
#pragma unroll
    for (int mt = 0; mt < 2; mt++)
#pragma unroll
        for (int nt = 0; nt < 8; nt++)
#pragma unroll
            for (int r = 0; r < 4; r++) acc[mt][nt][r] = 0.0f;

    const int lr  = lane & 7;
    const int lhk = (lane >> 3) & 1;
    const int lhi = lane >> 4;

#pragma unroll
    for (int t = 0; t < NSTAGE - 1; t++) {
        if (t < nkt) load_tile(t);
        CP_COMMIT();
    }
    CP_WAIT1();
    __syncthreads();

    for (int kt = 0; kt < nkt; kt++) {
        if (kt + NSTAGE - 1 < nkt) load_tile(kt + NSTAGE - 1);
        CP_COMMIT();

        const int st = kt % NSTAGE;
        const uint32_t asb = a_sm + (uint32_t)st * STG_WORDS * 4;
        const uint32_t bsb = b_sm + (uint32_t)st * STG_WORDS * 4;

#pragma unroll
        for (int ks = 0; ks < 4; ks++) {
            uint32_t af[2][4];
#pragma unroll
            for (int mt = 0; mt < 2; mt++) {
                const int row = wm + mt * 16 + lhk * 8 + lr;
                const int chk = ks * 2 + lhi;
                const uint32_t addr = asb + (uint32_t)row * 128
                                    + (uint32_t)((chk ^ (row & 7)) << 4);
                ldsm_x4(af[mt][0], af[mt][1], af[mt][2], af[mt][3], addr);
            }
            uint32_t bf[8][2];
#pragma unroll
            for (int p = 0; p < 4; p++) {
                const int row = wn + p * 16 + lhi * 8 + lr;
                const int chk = ks * 2 + lhk;
                const uint32_t addr = bsb + (uint32_t)row * 128
                                    + (uint32_t)((chk ^ (row & 7)) << 4);
                ldsm_x4(bf[2 * p][0], bf[2 * p][1], bf[2 * p + 1][0], bf[2 * p + 1][1], addr);
            }
#pragma unroll
            for (int mt = 0; mt < 2; mt++)
#pragma unroll
                for (int nt = 0; nt < 8; nt++)
                    mma_tf32(acc[mt][nt], af[mt], bf[nt]);
        }

        CP_WAIT1();
        __syncthreads();
    }

    // ---- epilogue ----
#pragma unroll
    for (int mt = 0; mt < 2; mt++) {
        const int r0 = wm + mt * 16 + g;
        float inv0 = 1.0f, inv1 = 1.0f;
        if (EPI == 2) {
            inv0 = 1.0f / g_rowsum[(size_t)(z + zoff) * T_TOK + m0 + r0];
            inv1 = 1.0f / g_rowsum[(size_t)(z + zoff) * T_TOK + m0 + r0 + 8];
        }
        float pos0 = 0.0f, pos1 = 0.0f;
        if (EPI == 3 || EPI == 4) {
            pos0 = (float)positions[m0 + r0];
            pos1 = (float)positions[m0 + r0 + 8];
        }
#pragma unroll
        for (int nt = 0; nt < 8; nt++) {
            const int col = n0 + wn + nt * 8 + 2 * tig;
            if (col < N) {
                float o0 = alpha * acc[mt][nt][0], o1 = alpha * acc[mt][nt][1];
                float o2 = alpha * acc[mt][nt][2], o3 = alpha * acc[mt][nt][3];
                if (EPI == 1) {
                    o0 = round_tf32(o0); o1 = round_tf32(o1);
                    o2 = round_tf32(o2); o3 = round_tf32(o3);
                } else if (EPI == 2) {
                    o0 = round_tf32(o0 * inv0); o1 = round_tf32(o1 * inv0);
                    o2 = round_tf32(o2 * inv1); o3 = round_tf32(o3 * inv1);
                } else if (EPI == 3) {
                    if (col >= QL + KVL) {
                        const int i = (col - (QL + KVL)) >> 1;
                        const float inv = powf(10000.0f, -(float)(2 * i) / 64.0f);
                        float sn, cs;
                        sincosf(pos0 * inv, &sn, &cs);
                        float a = o0, b = o1;
                        o0 = round_tf32(a * cs - b * sn);
                        o1 = round_tf32(a * sn + b * cs);
                        sincosf(pos1 * inv, &sn, &cs);
                        a = o2; b = o3;
                        o2 = round_tf32(a * cs - b * sn);
                        o3 = round_tf32(a * sn + b * cs);
                    }
                } else if (EPI == 4) {
                    const int dh = col % DH;
                    if (dh >= DN) {
                        const int i = (dh - DN) >> 1;
                        const float inv = powf(10000.0f, -(float)(2 * i) / 64.0f);
                        float sn, cs;
                        sincosf(pos0 * inv, &sn, &cs);
                        float a = o0, b = o1;
                        o0 = round_tf32(a * cs - b * sn);
                        o1 = round_tf32(a * sn + b * cs);
                        sincosf(pos1 * inv, &sn, &cs);
                        a = o2; b = o3;
                        o2 = round_tf32(a * cs - b * sn);
                        o3 = round_tf32(a * sn + b * cs);
                    } else {
                        o0 = round_tf32(o0); o1 = round_tf32(o1);
                        o2 = round_tf32(o2); o3 = round_tf32(o3);
                    }
                }
                *(float2*)&C[(size_t)(m0 + r0) * ldc + col]     = make_float2(o0, o1);
                *(float2*)&C[(size_t)(m0 + r0 + 8) * ldc + col] = make_float2(o2, o3);
            }
        }
    }
}

// ---------------- fused dual rmsnorm over g_qakva ----------------
__global__ void rmsnorm2_kernel(const float* __restrict__ gq, const float* __restrict__ gkv)
{
    const int row = blockIdx.x;
    const int sec = blockIdx.y;
    const int off = sec ? QL : 0;
    const int w   = sec ? KVL : QL;
    const float* gg = sec ? gkv : gq;
    float* p = g_qakva + (size_t)row * QKV_N + off;
    __shared__ float red[256];
    float s = 0.0f;
    for (int c = threadIdx.x; c < w; c += 256) { float v = p[c]; s += v * v; }
    red[threadIdx.x] = s;
    __syncthreads();
    for (int o = 128; o > 0; o >>= 1) {
        if (threadIdx.x < o) red[threadIdx.x] += red[threadIdx.x + o];
        __syncthreads();
    }
    const float r = rsqrtf(red[0] / (float)w + 1e-6f);
    for (int c = threadIdx.x; c < w; c += 256)
        p[c] = round_tf32(p[c] * r * gg[c]);
}

// ---------------- single-pass causal softmax (q offset q0) ----------------
__global__ __launch_bounds__(256)
void softmax_kernel(const int* __restrict__ positions, int q0)
{
    const int q = blockIdx.x + q0;
    const int h = blockIdx.y;
    float* row = g_s + ((size_t)h * T_TOK + q) * T_TOK;
    const int pq = positions[q];
    const int jmax = ((q >> 7) + 1) << 7;
    __shared__ float red[256];
    const int tid = threadIdx.x;

    float vals[8];
    int cnt = 0;
    float m = -INFINITY;
    for (int j = tid; j < jmax; j += 256) {
        float v = (positions[j] <= pq) ? row[j] : -INFINITY;
        vals[cnt++] = v;
        m = fmaxf(m, v);
    }
    red[tid] = m;
    __syncthreads();
    for (int o = 128; o > 0; o >>= 1) {
        if (tid < o) red[tid] = fmaxf(red[tid], red[tid + o]);
        __syncthreads();
    }
    m = red[0];
    __syncthreads();

    float s = 0.0f;
    cnt = 0;
    for (int j = tid; j < jmax; j += 256) {
        const float e = __expf(vals[cnt++] - m);
        s += e;
        row[j] = round_tf32(e);
    }
    red[tid] = s;
    __syncthreads();
    for (int o = 128; o > 0; o >>= 1) {
        if (tid < o) red[tid] += red[tid + o];
        __syncthreads();
    }
    if (tid == 0) g_rowsum[(size_t)h * T_TOK + q] = red[0];
}

// ---------------- launcher ----------------
extern "C" void kernel_launch(void* const* d_in, const int* in_sizes, int n_in,
                              void* d_out, int out_size)
{
    const int*   positions = (const int*)  d_in[0];
    const float* hidden    = (const float*)d_in[1];
    const float* wq_a      = (const float*)d_in[2];
    const float* gq        = (const float*)d_in[3];
    const float* wq_b      = (const float*)d_in[4];
    const float* wkv_a     = (const float*)d_in[5];
    const float* gkv       = (const float*)d_in[6];
    const float* wkv_b     = (const float*)d_in[7];
    const float* wo        = (const float*)d_in[8];
    float* out = (float*)d_out;

    float *qakva, *q, *kv, *s, *attn, *vt;
    float *hidr, *wqkva, *wqb, *wkvb, *wor;
    cudaGetSymbolAddress((void**)&qakva, g_qakva);
    cudaGetSymbolAddress((void**)&q,     g_q);
    cudaGetSymbolAddress((void**)&kv,    g_kv);
    cudaGetSymbolAddress((void**)&s,     g_s);
    cudaGetSymbolAddress((void**)&attn,  g_attn);
    cudaGetSymbolAddress((void**)&vt,    g_vt);
    cudaGetSymbolAddress((void**)&hidr,  g_hidr);
    cudaGetSymbolAddress((void**)&wqkva, g_wqkva);
    cudaGetSymbolAddress((void**)&wqb,   g_wqb);
    cudaGetSymbolAddress((void**)&wkvb,  g_wkvb);
    cudaGetSymbolAddress((void**)&wor,   g_wo);

    static cudaStream_t s1 = nullptr, s2 = nullptr;
    static cudaEvent_t evRoot = nullptr, evP1 = nullptr, evP2 = nullptr, evF = nullptr;
    static cudaEvent_t evM = nullptr, evS1 = nullptr, evJ = nullptr;
    static bool attr_done = false;
    if (!attr_done) {
        cudaFuncSetAttribute(tmma_gemm<false,false,3,false>,
            cudaFuncAttributeMaxDynamicSharedMemorySize, GEMM_SMEM_BYTES);
        cudaFuncSetAttribute(tmma_gemm<false,false,4,false>,
            cudaFuncAttributeMaxDynamicSharedMemorySize, GEMM_SMEM_BYTES);
        cudaFuncSetAttribute(tmma_gemm<false,false,1,false>,
            cudaFuncAttributeMaxDynamicSharedMemorySize, GEMM_SMEM_BYTES);
        cudaFuncSetAttribute(tmma_gemm<true,false,0,true>,
            cudaFuncAttributeMaxDynamicSharedMemorySize, GEMM_SMEM_BYTES);
        cudaFuncSetAttribute(tmma_gemm<false,true,2,false>,
            cudaFuncAttributeMaxDynamicSharedMemorySize, GEMM_SMEM_BYTES);
        cudaFuncSetAttribute(tmma_gemm<false,false,0,false>,
            cudaFuncAttributeMaxDynamicSharedMemorySize, GEMM_SMEM_BYTES);
        cudaStreamCreateWithFlags(&s1, cudaStreamNonBlocking);
        cudaStreamCreateWithFlags(&s2, cudaStreamNonBlocking);
        cudaEventCreateWithFlags(&evRoot, cudaEventDisableTiming);
        cudaEventCreateWithFlags(&evP1, cudaEventDisableTiming);
        cudaEventCreateWithFlags(&evP2, cudaEventDisableTiming);
        cudaEventCreateWithFlags(&evF,  cudaEventDisableTiming);
        cudaEventCreateWithFlags(&evM,  cudaEventDisableTiming);
        cudaEventCreateWithFlags(&evS1, cudaEventDisableTiming);
        cudaEventCreateWithFlags(&evJ,  cudaEventDisableTiming);
        attr_done = true;
    }

    const float scale = 1.0f / sqrtf((float)DH);
    const dim3 blk(256);
    const int  shm = GEMM_SMEM_BYTES;
    const dim3 tblk(32, 8);
    const int  QT = T_TOK / 128;     // 16 q-tiles
    const int  QTA = QT / 2;         // chain A: tiles 0..7

    // ---- root fork ----
    cudaEventRecord(evRoot, 0);
    cudaStreamWaitEvent(s1, evRoot, 0);
    cudaStreamWaitEvent(s2, evRoot, 0);

    // ---- preprocessing fork ----
    round_pass_kernel<<<1024, 256>>>(hidden, hidr, (int)((size_t)T_TOK * HID / 4));
    transpose_round_kernel<<<dim3(QL/32, HID/32), tblk, 0, s1>>>(wq_a, wqkva, HID, QL);
    transpose_round_kernel<<<dim3((KVL+DR)/32, HID/32), tblk, 0, s1>>>(
        wkv_a, wqkva + (size_t)QL * HID, HID, KVL+DR);
    transpose_round_kernel<<<dim3(NH*DH/32, QL/32), tblk, 0, s2>>>(wq_b, wqb, QL, NH*DH);
    transpose_round_kernel<<<dim3(NH*(DN+DV)/32, KVL/32), tblk, 0, s2>>>(
        wkv_b, wkvb, KVL, NH*(DN+DV));
    transpose_round_kernel<<<dim3(HID/32, NH*DV/32), tblk, 0, s2>>>(wo, wor, NH*DV, HID);
    cudaEventRecord(evP1, s1);
    cudaEventRecord(evP2, s2);
    cudaStreamWaitEvent(0, evP1, 0);

    // 1. [qa | kva] = hidr @ wqkva^T  (EPI3: rope k_pe cols at store)
    tmma_gemm<false,false,3,false><<<dim3((QKV_N+127)/128, T_TOK/128, 1), blk, shm>>>(
        hidr, wqkva, qakva, T_TOK, QKV_N, HID, HID, HID, QKV_N, 0, 0, 0, 1.0f,
        nullptr, 0, 0, 0, positions);

    // 2. rmsnorm both sections -> rounded
    rmsnorm2_kernel<<<dim3(T_TOK, 2), 256>>>(gq, gkv);

    // fork: s1 runs GEMM4 + vtrans while main runs GEMM3(+rope)
    cudaEventRecord(evF, 0);
    cudaStreamWaitEvent(s1, evF, 0);
    cudaStreamWaitEvent(s1, evP2, 0);
    cudaStreamWaitEvent(0,  evP2, 0);

    // 4. (s1) kv = ckv_ln @ wkvb^T   (EPI1 rounds)
    tmma_gemm<false,false,1,false><<<dim3(NH*(DN+DV)/128, T_TOK/128, 1), blk, shm, s1>>>(
        qakva + QL, wkvb, kv, T_TOK, NH*(DN+DV), KVL, QKV_N, KVL, NH*(DN+DV),
        0, 0, 0, 1.0f, nullptr, 0, 0, 0, nullptr);
    vtrans_kernel<<<dim3(T_TOK/32, DV/32, NH), tblk, 0, s1>>>();

    // 3. q = qa_ln @ wqb^T  (EPI4: rope pe + round nope at store)
    tmma_gemm<false,false,4,false><<<dim3(NH*DH/128, T_TOK/128, 1), blk, shm>>>(
        qakva, wqb, q, T_TOK, NH*DH, QL, QKV_N, QL, NH*DH, 0, 0, 0, 1.0f,
        nullptr, 0, 0, 0, positions);

    // cross-sync: both chains need q (main) and kv/vt (s1)
    cudaEventRecord(evM, 0);
    cudaEventRecord(evS1, s1);
    cudaStreamWaitEvent(0,  evS1, 0);
    cudaStreamWaitEvent(s1, evM, 0);

    // ---- attention + wo pipelined by q-range: chain A (tiles 0..7) on main,
    //      chain B (tiles 8..15) on s1. wo rows depend only on same-row attn. ----
    for (int c = 0; c < 2; c++) {
        cudaStream_t st = c ? s1 : (cudaStream_t)0;
        const int mo = c * QTA;                 // m-tile offset
        const int nx = c ? QT : QTA;            // n-tiles needed (causal)
        // scores = scale * q @ [k_nope | k_pe]^T
        tmma_gemm<true,false,0,true><<<dim3(nx, QTA, NH), blk, shm, st>>>(
            q, kv, s, T_TOK, T_TOK, DH, NH*DH, NH*(DN+DV), T_TOK,
            (long long)DH, (long long)(DN+DV), (long long)T_TOK*T_TOK, scale,
            qakva + QL + KVL, QKV_N, 0, mo, nullptr);
        // softmax
        softmax_kernel<<<dim3(T_TOK/2, NH), 256, 0, st>>>(positions, mo * 128);
        // PV + row-normalize (K clamp, heavy-first)
        tmma_gemm<false,true,2,false><<<dim3(1, QTA, NH), blk, shm, st>>>(
            s, vt, attn, T_TOK, DV, T_TOK, T_TOK, T_TOK, NH*DV,
            (long long)T_TOK*T_TOK, (long long)DV*T_TOK, (long long)DV, 1.0f,
            nullptr, 0, 0, mo, nullptr);
        // wo for this q-range
        tmma_gemm<false,false,0,false><<<dim3(HID/128, QTA, 1), blk, shm, st>>>(
            attn, wor, out, T_TOK, HID, NH*DV, NH*DV, NH*DV, HID, 0, 0, 0, 1.0f,
            nullptr, 0, 0, mo, nullptr);
    }

    // join
    cudaEventRecord(evJ, s1);
    cudaStreamWaitEvent(0, evJ, 0);
}